// round 13
// baseline (speedup 1.0000x reference)
#include <cuda_runtime.h>
#include <cuda_fp16.h>
#include <cstdint>

#define SEQ     4096
#define BATCH   4
#define DMODEL  512
#define FFDIM   2048
#define MTOT    (BATCH*SEQ)
#define NQKV    (3*DMODEL)    // 1536

// GEMM tile config: CTA 256x128, 8 warps (4M x 2N), warp tile 64x64, BK=32.
#define BMT 256
#define BNT 128
#define NST 3
#define ASZ 16384             // 256 rows * 64B (32 fp16)
#define BSZ 8192              // 128 rows * 64B
#define STG (ASZ + BSZ)       // 24KB per stage
#define GEMM_SMEM (NST*STG)   // 72KB dynamic

// ---------------- scratch ----------------
__device__ __align__(256) __half g_s   [(size_t)BATCH*SEQ*SEQ];     // fp16 scores/probs
__device__ __align__(256) __half g_xh  [(size_t)MTOT*DMODEL];
__device__ __align__(256) __half g_qkv [(size_t)MTOT*NQKV];         // Q|K|V fp16
__device__ __align__(256) __half g_vth [(size_t)MTOT*DMODEL];       // V^T per batch
__device__ __align__(256) __half g_ah  [(size_t)MTOT*DMODEL];
__device__ __align__(256) float  g_u   [(size_t)MTOT*DMODEL];
__device__ __align__(256) float  g_h   [(size_t)MTOT*DMODEL];
__device__ __align__(256) __half g_hh  [(size_t)MTOT*DMODEL];
__device__ __align__(256) __half g_fh  [(size_t)MTOT*FFDIM];
__device__ __align__(256) __half g_wqkv[NQKV*DMODEL];
__device__ __align__(256) float  g_qkvb[NQKV];
__device__ __align__(256) __half g_wuh [DMODEL*DMODEL];
__device__ __align__(256) __half g_f1h [FFDIM*DMODEL];
__device__ __align__(256) __half g_f2h [DMODEL*FFDIM];

// ---------------- PTX helpers ----------------
static __device__ __forceinline__ uint32_t smem_u32(const void* p) {
    uint32_t a;
    asm("{ .reg .u64 t; cvta.to.shared.u64 t, %1; cvt.u32.u64 %0, t; }" : "=r"(a) : "l"(p));
    return a;
}
#define CP_ASYNC16(saddr, gptr) \
    asm volatile("cp.async.cg.shared.global [%0], [%1], 16;" :: "r"(saddr), "l"(gptr) : "memory")
#define CP_COMMIT() asm volatile("cp.async.commit_group;" ::: "memory")
#define CP_WAIT1()  asm volatile("cp.async.wait_group 1;"  ::: "memory")

#define LDSM4(r, addr) \
    asm volatile("ldmatrix.sync.aligned.m8n8.x4.shared.b16 {%0,%1,%2,%3}, [%4];" \
        : "=r"((r)[0]), "=r"((r)[1]), "=r"((r)[2]), "=r"((r)[3]) : "r"(addr))

#define MMA16816(c, a, b) \
    asm volatile("mma.sync.aligned.m16n8k16.row.col.f32.f16.f16.f32 " \
        "{%0,%1,%2,%3}, {%4,%5,%6,%7}, {%8,%9}, {%0,%1,%2,%3};" \
        : "+f"((c)[0]), "+f"((c)[1]), "+f"((c)[2]), "+f"((c)[3]) \
        : "r"((a)[0]), "r"((a)[1]), "r"((a)[2]), "r"((a)[3]), "r"((b)[0]), "r"((b)[1]))

static __device__ __forceinline__ uint32_t pack2(__half a, __half b) {
    return (uint32_t)__half_as_ushort(a) | ((uint32_t)__half_as_ushort(b) << 16);
}

// ---------------------------------------------------------------------------
// HMMA GEMM, single-pass fp16. A:[M,K] K-major (lda). B:[N,K] K-major (ldb).
// D = alpha*A@B^T + bias; outputs fp32 and/or fp16 (ld=N_).
// CTA 256x128, BK=32, 3-stage cp.async (72KB dyn smem), 8 warps (4M x 2N),
// warp tile 64x64 -> tensor-pipe bound (smem reads/output halved vs 64x32).
// ---------------------------------------------------------------------------
template<bool RELU>
__global__ void __launch_bounds__(256) mma_gemm(
    const __half* __restrict__ A, long long lda, long long sAz,
    const __half* __restrict__ B, long long ldb, long long sBz,
    const float* __restrict__ bias, float alpha,
    float* __restrict__ outF, __half* __restrict__ outH,
    int N_, long long sCz, int K)
{
    extern __shared__ __align__(1024) char smem[];
    const uint32_t sbase = smem_u32(smem);
    const int tid  = threadIdx.x;
    const int lane = tid & 31;
    const int wid  = tid >> 5;
    const int warp_m = (wid & 3) * 64;   // 4 M groups
    const int warp_n = (wid >> 2) * 64;  // 2 N groups

    const long long z    = blockIdx.z;
    const long long arow = (long long)blockIdx.y * BMT;
    const long long brow = (long long)blockIdx.x * BNT;

    const __half* A_z = A + z * sAz;
    const __half* B_z = B + z * sBz;

    float acc[4][8][4];
#pragma unroll
    for (int i = 0; i < 4; i++)
#pragma unroll
        for (int j = 0; j < 8; j++)
#pragma unroll
            for (int q = 0; q < 4; q++) acc[i][j][q] = 0.f;

    // cp.async slots: A 1024 chunks (4/thr), B 512 chunks (2/thr); 64B rows
    long long gA[4]; uint32_t swA[4];
#pragma unroll
    for (int q = 0; q < 4; q++) {
        int slot = tid + q*256, r = slot >> 2, c = slot & 3;
        gA[q]  = (arow + r) * lda + c*8;
        swA[q] = r*64 + (((c ^ ((r >> 1) & 3)) << 4));
    }
    long long gB[2]; uint32_t swB[2];
#pragma unroll
    for (int q = 0; q < 2; q++) {
        int slot = tid + q*256, r = slot >> 2, c = slot & 3;
        gB[q]  = (brow + r) * ldb + c*8;
        swB[q] = r*64 + (((c ^ ((r >> 1) & 3)) << 4));
    }

    const int nch = K >> 5;

#define ISSUE(ch) { \
        const int st_ = (ch) % NST; \
        const long long kof_ = (long long)(ch) * 32; \
        const uint32_t sA_ = sbase + st_*STG; \
        const uint32_t sB_ = sA_ + ASZ; \
        CP_ASYNC16(sA_ + swA[0], A_z + gA[0] + kof_); \
        CP_ASYNC16(sA_ + swA[1], A_z + gA[1] + kof_); \
        CP_ASYNC16(sA_ + swA[2], A_z + gA[2] + kof_); \
        CP_ASYNC16(sA_ + swA[3], A_z + gA[3] + kof_); \
        CP_ASYNC16(sB_ + swB[0], B_z + gB[0] + kof_); \
        CP_ASYNC16(sB_ + swB[1], B_z + gB[1] + kof_); }

    ISSUE(0); CP_COMMIT();
    ISSUE(1); CP_COMMIT();

    const int rA   = lane & 15;
    const int kcA  = lane >> 4;
    const int swzA = (rA >> 1) & 3;
    const uint32_t aBase = (uint32_t)(warp_m + rA) * 64;
    const int rB   = ((lane >> 4) << 3) + (lane & 7);
    const int kcB  = (lane >> 3) & 1;
    const int swzB = (rB >> 1) & 3;
    const uint32_t bBase = (uint32_t)(warp_n + rB) * 64;

#pragma unroll 1
    for (int j = 0; j < nch; j++) {
        CP_WAIT1();
        __syncthreads();
        if (j + 2 < nch) { ISSUE(j + 2); }
        CP_COMMIT();

        const uint32_t sA = sbase + (j % NST) * STG;
        const uint32_t sB = sA + ASZ;
#pragma unroll
        for (int ks = 0; ks < 2; ks++) {
            uint32_t af[4][4];
            uint32_t bf[8][2];
#pragma unroll
            for (int mt = 0; mt < 4; mt++) {
                uint32_t addr = sA + aBase + mt*1024 + ((uint32_t)((ks*2 + kcA) ^ swzA) << 4);
                LDSM4(af[mt], addr);
            }
#pragma unroll
            for (int nt2 = 0; nt2 < 4; nt2++) {
                uint32_t r[4];
                uint32_t addr = sB + bBase + nt2*1024 + ((uint32_t)((ks*2 + kcB) ^ swzB) << 4);
                LDSM4(r, addr);
                bf[2*nt2][0]   = r[0]; bf[2*nt2][1]   = r[1];
                bf[2*nt2+1][0] = r[2]; bf[2*nt2+1][1] = r[3];
            }
#pragma unroll
            for (int mt = 0; mt < 4; mt++)
#pragma unroll
                for (int nt = 0; nt < 8; nt++)
                    MMA16816(acc[mt][nt], af[mt], bf[nt]);
        }
    }
#undef ISSUE

    // -------- epilogue --------
    const long long mBase = arow + warp_m + (lane >> 2);
    const int       nBase = (int)brow + warp_n + (lane & 3) * 2;
    const long long czB   = z * sCz;
#pragma unroll
    for (int mt = 0; mt < 4; mt++) {
        const long long ra = mBase + mt*16;
        const long long rb = ra + 8;
#pragma unroll
        for (int nt = 0; nt < 8; nt++) {
            const int col = nBase + nt*8;
            float v0 = acc[mt][nt][0] * alpha;
            float v1 = acc[mt][nt][1] * alpha;
            float v2 = acc[mt][nt][2] * alpha;
            float v3 = acc[mt][nt][3] * alpha;
            if (bias) {
                float2 bb = *reinterpret_cast<const float2*>(bias + col);
                v0 += bb.x; v1 += bb.y; v2 += bb.x; v3 += bb.y;
            }
            if (RELU) {
                v0 = fmaxf(v0, 0.f); v1 = fmaxf(v1, 0.f);
                v2 = fmaxf(v2, 0.f); v3 = fmaxf(v3, 0.f);
            }
            if (outF) {
                *reinterpret_cast<float2*>(outF + czB + ra*N_ + col) = make_float2(v0, v1);
                *reinterpret_cast<float2*>(outF + czB + rb*N_ + col) = make_float2(v2, v3);
            }
            if (outH) {
                *reinterpret_cast<uint32_t*>(outH + czB + ra*N_ + col) =
                    pack2(__float2half_rn(v0), __float2half_rn(v1));
                *reinterpret_cast<uint32_t*>(outH + czB + rb*N_ + col) =
                    pack2(__float2half_rn(v2), __float2half_rn(v3));
            }
        }
    }
}

// fp32 -> fp16 elementwise
__global__ void __launch_bounds__(256) conv_h(
    const float* __restrict__ in, __half* __restrict__ oh, int n4)
{
    int i = blockIdx.x * 256 + threadIdx.x;
    if (i >= n4) return;
    float4 v = reinterpret_cast<const float4*>(in)[i];
    reinterpret_cast<uint2*>(oh)[i] = make_uint2(
        pack2(__float2half_rn(v.x), __float2half_rn(v.y)),
        pack2(__float2half_rn(v.z), __float2half_rn(v.w)));
}

// transpose + fp16: in fp32 [R,C] -> out fp16 [C,R]
__global__ void tconv(
    const float* __restrict__ in,
    __half* __restrict__ oh,
    int R, int C)
{
    __shared__ float t[32][33];
    const int c0 = blockIdx.x * 32, r0 = blockIdx.y * 32;
#pragma unroll
    for (int dy = 0; dy < 32; dy += 8)
        t[threadIdx.y + dy][threadIdx.x] =
            in[(long long)(r0 + threadIdx.y + dy) * C + c0 + threadIdx.x];
    __syncthreads();
#pragma unroll
    for (int dy = 0; dy < 32; dy += 8) {
        float v = t[threadIdx.x][threadIdx.y + dy];
        long long o = (long long)(c0 + threadIdx.y + dy) * R + r0 + threadIdx.x;
        oh[o] = __float2half_rn(v);
    }
}

// fp16 transpose: in [R rows, ldIn] (C cols used) -> out [C, R]; batched z
__global__ void tconvh(
    const __half* __restrict__ in, long long ldIn, long long sIn,
    __half* __restrict__ oh, long long sOut,
    int R, int C)
{
    __shared__ __half t[32][34];
    const int c0 = blockIdx.x * 32, r0 = blockIdx.y * 32;
    in += blockIdx.z * sIn; oh += blockIdx.z * sOut;
#pragma unroll
    for (int dy = 0; dy < 32; dy += 8)
        t[threadIdx.y + dy][threadIdx.x] =
            in[(long long)(r0 + threadIdx.y + dy) * ldIn + c0 + threadIdx.x];
    __syncthreads();
#pragma unroll
    for (int dy = 0; dy < 32; dy += 8) {
        long long o = (long long)(c0 + threadIdx.y + dy) * R + r0 + threadIdx.x;
        oh[o] = t[threadIdx.x][threadIdx.y + dy];
    }
}

// concat 3 biases -> g_qkvb
__global__ void bias_cat(const float* __restrict__ qb, const float* __restrict__ kb,
                         const float* __restrict__ vb, float* __restrict__ o)
{
    int i = blockIdx.x * 256 + threadIdx.x;
    if (i < DMODEL)            o[i] = qb[i];
    else if (i < 2*DMODEL)     o[i] = kb[i - DMODEL];
    else if (i < 3*DMODEL)     o[i] = vb[i - 2*DMODEL];
}

// softmax over 4096 fp16 in place
__global__ void __launch_bounds__(256) softmax_k(__half* __restrict__ S)
{
    const long long row = blockIdx.x;
    __half* p = S + row * (long long)SEQ;
    const int tid = threadIdx.x, lane = tid & 31, warp = tid >> 5;
    __shared__ float red[8];

    float v[16];
    float mx = -1e30f;
#pragma unroll
    for (int i = 0; i < 16; i++) { v[i] = __half2float(p[i*256 + tid]); mx = fmaxf(mx, v[i]); }
#pragma unroll
    for (int o = 16; o > 0; o >>= 1) mx = fmaxf(mx, __shfl_xor_sync(0xffffffffu, mx, o));
    if (!lane) red[warp] = mx;
    __syncthreads();
    mx = red[0];
#pragma unroll
    for (int w = 1; w < 8; w++) mx = fmaxf(mx, red[w]);
    __syncthreads();
    float sm = 0.f;
#pragma unroll
    for (int i = 0; i < 16; i++) { v[i] = __expf(v[i] - mx); sm += v[i]; }
#pragma unroll
    for (int o = 16; o > 0; o >>= 1) sm += __shfl_xor_sync(0xffffffffu, sm, o);
    if (!lane) red[warp] = sm;
    __syncthreads();
    float inv = __frcp_rn(red[0]+red[1]+red[2]+red[3]+red[4]+red[5]+red[6]+red[7]);
#pragma unroll
    for (int i = 0; i < 16; i++)
        p[i*256 + tid] = __float2half_rn(v[i] * inv);
}

// out = LN(X+U); optionally fp16 too
template<bool HL>
__global__ void __launch_bounds__(128) add_ln_k(
    const float* __restrict__ X, const float* __restrict__ U,
    const float* __restrict__ g, const float* __restrict__ b,
    float* __restrict__ outF, __half* __restrict__ outH)
{
    const long long row = blockIdx.x;
    const int tid = threadIdx.x, lane = tid & 31, warp = tid >> 5;
    __shared__ float red[4];

    float4 xv = reinterpret_cast<const float4*>(X + row * DMODEL)[tid];
    float4 uv = reinterpret_cast<const float4*>(U + row * DMODEL)[tid];
    float4 s = make_float4(xv.x+uv.x, xv.y+uv.y, xv.z+uv.z, xv.w+uv.w);

    float pp = s.x + s.y + s.z + s.w;
#pragma unroll
    for (int o = 16; o > 0; o >>= 1) pp += __shfl_xor_sync(0xffffffffu, pp, o);
    if (!lane) red[warp] = pp;
    __syncthreads();
    float mu = (red[0]+red[1]+red[2]+red[3]) * (1.f/DMODEL);
    __syncthreads();
    float dx = s.x-mu, dy = s.y-mu, dz = s.z-mu, dw = s.w-mu;
    pp = dx*dx + dy*dy + dz*dz + dw*dw;
#pragma unroll
    for (int o = 16; o > 0; o >>= 1) pp += __shfl_xor_sync(0xffffffffu, pp, o);
    if (!lane) red[warp] = pp;
    __syncthreads();
    float inv = rsqrtf((red[0]+red[1]+red[2]+red[3]) * (1.f/DMODEL) + 1e-5f);

    float4 gv = reinterpret_cast<const float4*>(g)[tid];
    float4 bv = reinterpret_cast<const float4*>(b)[tid];
    float4 o4;
    o4.x = dx*inv*gv.x + bv.x;
    o4.y = dy*inv*gv.y + bv.y;
    o4.z = dz*inv*gv.z + bv.z;
    o4.w = dw*inv*gv.w + bv.w;
    reinterpret_cast<float4*>(outF + row * DMODEL)[tid] = o4;
    if (HL) {
        reinterpret_cast<uint2*>(outH + row * DMODEL)[tid] = make_uint2(
            pack2(__float2half_rn(o4.x), __float2half_rn(o4.y)),
            pack2(__float2half_rn(o4.z), __float2half_rn(o4.w)));
    }
}

// ---------------------------------------------------------------------------
extern "C" void kernel_launch(void* const* d_in, const int* in_sizes, int n_in,
                              void* d_out, int out_size)
{
    (void)in_sizes; (void)n_in; (void)out_size;
    const float* x     = (const float*)d_in[0];
    const float* Wq_w  = (const float*)d_in[1];
    const float* Wq_b  = (const float*)d_in[2];
    const float* Wk_w  = (const float*)d_in[3];
    const float* Wk_b  = (const float*)d_in[4];
    const float* Wv_w  = (const float*)d_in[5];
    const float* Wv_b  = (const float*)d_in[6];
    const float* Wu_w  = (const float*)d_in[7];
    const float* Wu_b  = (const float*)d_in[8];
    const float* ln1_g = (const float*)d_in[9];
    const float* ln1_b = (const float*)d_in[10];
    const float* ff1_w = (const float*)d_in[11];
    const float* ff1_b = (const float*)d_in[12];
    const float* ff2_w = (const float*)d_in[13];
    const float* ff2_b = (const float*)d_in[14];
    const float* ln2_g = (const float*)d_in[15];
    const float* ln2_b = (const float*)d_in[16];
    float* out = (float*)d_out;

    cudaFuncSetAttribute(mma_gemm<false>, cudaFuncAttributeMaxDynamicSharedMemorySize, GEMM_SMEM);
    cudaFuncSetAttribute(mma_gemm<true>,  cudaFuncAttributeMaxDynamicSharedMemorySize, GEMM_SMEM);

#define SYM(T, n, s) T* n; { void* p_; cudaGetSymbolAddress(&p_, s); n = (T*)p_; }
    SYM(__half, s, g_s) SYM(float, u, g_u) SYM(float, h, g_h)
    SYM(__half, xh, g_xh)
    SYM(__half, qkv, g_qkv)
    SYM(__half, vth, g_vth)
    SYM(__half, ah, g_ah)
    SYM(__half, hh, g_hh)
    SYM(__half, fh, g_fh)
    SYM(__half, wqkv, g_wqkv)
    SYM(float,  qkvb, g_qkvb)
    SYM(__half, wuh, g_wuh)
    SYM(__half, f1h, g_f1h)
    SYM(__half, f2h, g_f2h)
#undef SYM

    const long long QS   = (long long)SEQ * DMODEL;
    const long long SS   = (long long)SEQ * SEQ;
    const long long QKVS = (long long)SEQ * NQKV;

    // 0: x -> fp16
    conv_h<<<(MTOT*DMODEL/4 + 255)/256, 256>>>(x, xh, MTOT*DMODEL/4);
    // 1-3: Wq|Wk|Wv transposed into combined [1536,512] fp16
    tconv<<<dim3(16,16,1), dim3(32,8)>>>(Wq_w, wqkv,                           DMODEL, DMODEL);
    tconv<<<dim3(16,16,1), dim3(32,8)>>>(Wk_w, wqkv + (size_t)DMODEL*DMODEL,   DMODEL, DMODEL);
    tconv<<<dim3(16,16,1), dim3(32,8)>>>(Wv_w, wqkv + (size_t)2*DMODEL*DMODEL, DMODEL, DMODEL);
    // 4: bias concat
    bias_cat<<<(NQKV + 255)/256, 256>>>(Wq_b, Wk_b, Wv_b, qkvb);

    // 5: fused QKV GEMM [16384,1536]
    mma_gemm<false><<<dim3(NQKV/BNT, MTOT/BMT, 1), 256, GEMM_SMEM>>>(
        xh, DMODEL, 0, wqkv, DMODEL, 0, qkvb, 1.f, nullptr, qkv, NQKV, 0, DMODEL);

    // 6: scores = QK^T/8 -> fp16
    mma_gemm<false><<<dim3(SEQ/BNT, SEQ/BMT, BATCH), 256, GEMM_SMEM>>>(
        qkv, NQKV, QKVS, qkv + DMODEL, NQKV, QKVS,
        nullptr, 0.125f, nullptr, s, SEQ, SS, DMODEL);

    // 7: softmax fp16 in place
    softmax_k<<<MTOT, 256>>>(s);

    // 8: V^T per batch
    tconvh<<<dim3(DMODEL/32, SEQ/32, BATCH), dim3(32,8)>>>(
        qkv + 2*DMODEL, NQKV, QKVS, vth, QS, SEQ, DMODEL);

    // 9: attn = P @ V
    mma_gemm<false><<<dim3(DMODEL/BNT, SEQ/BMT, BATCH), 256, GEMM_SMEM>>>(
        s, SEQ, SS, vth, SEQ, QS, nullptr, 1.f, nullptr, ah, DMODEL, QS, SEQ);

    // 10: Wu transpose; 11: unify
    tconv<<<dim3(16,16,1), dim3(32,8)>>>(Wu_w, wuh, DMODEL, DMODEL);
    mma_gemm<false><<<dim3(DMODEL/BNT, MTOT/BMT, 1), 256, GEMM_SMEM>>>(
        ah, DMODEL, 0, wuh, DMODEL, 0, Wu_b, 1.f, u, nullptr, DMODEL, 0, DMODEL);

    // 12: h = LN1(x+u)
    add_ln_k<true><<<MTOT, 128>>>(x, u, ln1_g, ln1_b, h, hh);

    // 13: ff1 weights; 14: ff1 (relu)
    tconv<<<dim3(FFDIM/32,16,1), dim3(32,8)>>>(ff1_w, f1h, DMODEL, FFDIM);
    mma_gemm<true><<<dim3(FFDIM/BNT, MTOT/BMT, 1), 256, GEMM_SMEM>>>(
        hh, DMODEL, 0, f1h, DMODEL, 0, ff1_b, 1.f, nullptr, fh, FFDIM, 0, DMODEL);

    // 15: ff2 weights; 16: ff2
    tconv<<<dim3(16,FFDIM/32,1), dim3(32,8)>>>(ff2_w, f2h, FFDIM, DMODEL);
    mma_gemm<false><<<dim3(DMODEL/BNT, MTOT/BMT, 1), 256, GEMM_SMEM>>>(
        fh, FFDIM, 0, f2h, FFDIM, 0, ff2_b, 1.f, u, nullptr, DMODEL, 0, FFDIM);

    // 17: out = LN2(h + ffwd)
    add_ln_k<false><<<MTOT, 128>>>(h, u, ln2_g, ln2_b, out, nullptr);
}

// round 14
// speedup vs baseline: 1.2202x; 1.2202x over previous
#include <cuda_runtime.h>
#include <cuda_fp16.h>
#include <cstdint>

#define SEQ     4096
#define BATCH   4
#define DMODEL  512
#define FFDIM   2048
#define MTOT    (BATCH*SEQ)
#define NQKV    (3*DMODEL)    // 1536

// GEMM tile config: CTA 128x128, 8 warps (2M x 4N), warp tile 64x32, BK=32.
// 4-stage cp.async pipeline (prefetch depth 3), 64KB dynamic smem, 2 CTAs/SM.
#define BMT 128
#define BNT 128
#define NST 4
#define ASZ 8192              // 128 rows * 64B (32 fp16)
#define STG (2*ASZ)           // A + B per stage (16KB)
#define GEMM_SMEM (NST*STG)   // 64KB dynamic

// ---------------- scratch ----------------
__device__ __align__(256) __half g_s   [(size_t)BATCH*SEQ*SEQ];     // fp16 scores/probs
__device__ __align__(256) __half g_xh  [(size_t)MTOT*DMODEL];
__device__ __align__(256) __half g_qkv [(size_t)MTOT*NQKV];         // Q|K|V fp16
__device__ __align__(256) __half g_vth [(size_t)MTOT*DMODEL];       // V^T per batch
__device__ __align__(256) __half g_ah  [(size_t)MTOT*DMODEL];
__device__ __align__(256) float  g_u   [(size_t)MTOT*DMODEL];
__device__ __align__(256) float  g_h   [(size_t)MTOT*DMODEL];
__device__ __align__(256) __half g_hh  [(size_t)MTOT*DMODEL];
__device__ __align__(256) __half g_fh  [(size_t)MTOT*FFDIM];
__device__ __align__(256) __half g_wqkv[NQKV*DMODEL];
__device__ __align__(256) float  g_qkvb[NQKV];
__device__ __align__(256) __half g_wuh [DMODEL*DMODEL];
__device__ __align__(256) __half g_f1h [FFDIM*DMODEL];
__device__ __align__(256) __half g_f2h [DMODEL*FFDIM];

// ---------------- PTX helpers ----------------
static __device__ __forceinline__ uint32_t smem_u32(const void* p) {
    uint32_t a;
    asm("{ .reg .u64 t; cvta.to.shared.u64 t, %1; cvt.u32.u64 %0, t; }" : "=r"(a) : "l"(p));
    return a;
}
#define CP_ASYNC16(saddr, gptr) \
    asm volatile("cp.async.cg.shared.global [%0], [%1], 16;" :: "r"(saddr), "l"(gptr) : "memory")
#define CP_COMMIT() asm volatile("cp.async.commit_group;" ::: "memory")
#define CP_WAIT2()  asm volatile("cp.async.wait_group 2;"  ::: "memory")

#define LDSM4(r, addr) \
    asm volatile("ldmatrix.sync.aligned.m8n8.x4.shared.b16 {%0,%1,%2,%3}, [%4];" \
        : "=r"((r)[0]), "=r"((r)[1]), "=r"((r)[2]), "=r"((r)[3]) : "r"(addr))

#define MMA16816(c, a, b) \
    asm volatile("mma.sync.aligned.m16n8k16.row.col.f32.f16.f16.f32 " \
        "{%0,%1,%2,%3}, {%4,%5,%6,%7}, {%8,%9}, {%0,%1,%2,%3};" \
        : "+f"((c)[0]), "+f"((c)[1]), "+f"((c)[2]), "+f"((c)[3]) \
        : "r"((a)[0]), "r"((a)[1]), "r"((a)[2]), "r"((a)[3]), "r"((b)[0]), "r"((b)[1]))

static __device__ __forceinline__ uint32_t pack2(__half a, __half b) {
    return (uint32_t)__half_as_ushort(a) | ((uint32_t)__half_as_ushort(b) << 16);
}

// ---------------------------------------------------------------------------
// HMMA GEMM, single-pass fp16. A:[M,K] K-major (lda). B:[N,K] K-major (ldb).
// D = alpha*A@B^T + bias; outputs fp32 and/or fp16 (ld=N_).
// CTA 128x128, BK=32, 4-stage cp.async (wait_group 2), 8 warps (2M x 4N).
// ---------------------------------------------------------------------------
template<bool RELU>
__global__ void __launch_bounds__(256, 2) mma_gemm(
    const __half* __restrict__ A, long long lda, long long sAz,
    const __half* __restrict__ B, long long ldb, long long sBz,
    const float* __restrict__ bias, float alpha,
    float* __restrict__ outF, __half* __restrict__ outH,
    int N_, long long sCz, int K)
{
    extern __shared__ __align__(1024) char smem[];
    const uint32_t sbase = smem_u32(smem);
    const int tid  = threadIdx.x;
    const int lane = tid & 31;
    const int wid  = tid >> 5;
    const int warp_m = (wid & 1) * 64;
    const int warp_n = (wid >> 1) * 32;

    const long long z    = blockIdx.z;
    const long long arow = (long long)blockIdx.y * BMT;
    const long long brow = (long long)blockIdx.x * BNT;

    const __half* A_z = A + z * sAz;
    const __half* B_z = B + z * sBz;

    float acc[4][4][4];
#pragma unroll
    for (int i = 0; i < 4; i++)
#pragma unroll
        for (int j = 0; j < 4; j++)
#pragma unroll
            for (int q = 0; q < 4; q++) acc[i][j][q] = 0.f;

    const int r0 = tid >> 2,         c0 = tid & 3;
    const int r1 = (tid + 256) >> 2, c1 = (tid + 256) & 3;
    const uint32_t sw0 = r0*64 + (((c0 ^ ((r0 >> 1) & 3)) << 4));
    const uint32_t sw1 = r1*64 + (((c1 ^ ((r1 >> 1) & 3)) << 4));
    const long long gA0 = (arow + r0) * lda + c0*8;
    const long long gA1 = (arow + r1) * lda + c1*8;
    const long long gB0 = (brow + r0) * ldb + c0*8;
    const long long gB1 = (brow + r1) * ldb + c1*8;

    const int nch = K >> 5;

#define ISSUE(ch) { \
        const int st_ = (ch) % NST; \
        const long long kof_ = (long long)(ch) * 32; \
        const uint32_t sA_ = sbase + st_*STG; \
        const uint32_t sB_ = sA_ + ASZ; \
        CP_ASYNC16(sA_ + sw0, A_z + gA0 + kof_); \
        CP_ASYNC16(sA_ + sw1, A_z + gA1 + kof_); \
        CP_ASYNC16(sB_ + sw0, B_z + gB0 + kof_); \
        CP_ASYNC16(sB_ + sw1, B_z + gB1 + kof_); }

    ISSUE(0); CP_COMMIT();
    ISSUE(1); CP_COMMIT();
    ISSUE(2); CP_COMMIT();

    const int rA   = lane & 15;
    const int kcA  = lane >> 4;
    const int swzA = (rA >> 1) & 3;
    const uint32_t aBase = (uint32_t)(warp_m + rA) * 64;
    const int rB   = ((lane >> 4) << 3) + (lane & 7);
    const int kcB  = (lane >> 3) & 1;
    const int swzB = (rB >> 1) & 3;
    const uint32_t bBase = (uint32_t)(warp_n + rB) * 64;

#pragma unroll 1
    for (int j = 0; j < nch; j++) {
        CP_WAIT2();
        __syncthreads();
        if (j + 3 < nch) { ISSUE(j + 3); }
        CP_COMMIT();

        const uint32_t sA = sbase + (j % NST) * STG;
        const uint32_t sB = sA + ASZ;
#pragma unroll
        for (int ks = 0; ks < 2; ks++) {
            uint32_t af[4][4];
            uint32_t bf[4][2];
#pragma unroll
            for (int mt = 0; mt < 4; mt++) {
                uint32_t addr = sA + aBase + mt*1024 + ((uint32_t)((ks*2 + kcA) ^ swzA) << 4);
                LDSM4(af[mt], addr);
            }
#pragma unroll
            for (int nt2 = 0; nt2 < 2; nt2++) {
                uint32_t r[4];
                uint32_t addr = sB + bBase + nt2*1024 + ((uint32_t)((ks*2 + kcB) ^ swzB) << 4);
                LDSM4(r, addr);
                bf[2*nt2][0]   = r[0]; bf[2*nt2][1]   = r[1];
                bf[2*nt2+1][0] = r[2]; bf[2*nt2+1][1] = r[3];
            }
#pragma unroll
            for (int mt = 0; mt < 4; mt++)
#pragma unroll
                for (int nt = 0; nt < 4; nt++)
                    MMA16816(acc[mt][nt], af[mt], bf[nt]);
        }
    }
#undef ISSUE

    // -------- epilogue --------
    const long long mBase = arow + warp_m + (lane >> 2);
    const int       nBase = (int)brow + warp_n + (lane & 3) * 2;
    const long long czB   = z * sCz;
#pragma unroll
    for (int mt = 0; mt < 4; mt++) {
        const long long ra = mBase + mt*16;
        const long long rb = ra + 8;
#pragma unroll
        for (int nt = 0; nt < 4; nt++) {
            const int col = nBase + nt*8;
            float v0 = acc[mt][nt][0] * alpha;
            float v1 = acc[mt][nt][1] * alpha;
            float v2 = acc[mt][nt][2] * alpha;
            float v3 = acc[mt][nt][3] * alpha;
            if (bias) {
                float2 bb = *reinterpret_cast<const float2*>(bias + col);
                v0 += bb.x; v1 += bb.y; v2 += bb.x; v3 += bb.y;
            }
            if (RELU) {
                v0 = fmaxf(v0, 0.f); v1 = fmaxf(v1, 0.f);
                v2 = fmaxf(v2, 0.f); v3 = fmaxf(v3, 0.f);
            }
            if (outF) {
                *reinterpret_cast<float2*>(outF + czB + ra*N_ + col) = make_float2(v0, v1);
                *reinterpret_cast<float2*>(outF + czB + rb*N_ + col) = make_float2(v2, v3);
            }
            if (outH) {
                *reinterpret_cast<uint32_t*>(outH + czB + ra*N_ + col) =
                    pack2(__float2half_rn(v0), __float2half_rn(v1));
                *reinterpret_cast<uint32_t*>(outH + czB + rb*N_ + col) =
                    pack2(__float2half_rn(v2), __float2half_rn(v3));
            }
        }
    }
}

// fp32 -> fp16 elementwise
__global__ void __launch_bounds__(256) conv_h(
    const float* __restrict__ in, __half* __restrict__ oh, int n4)
{
    int i = blockIdx.x * 256 + threadIdx.x;
    if (i >= n4) return;
    float4 v = reinterpret_cast<const float4*>(in)[i];
    reinterpret_cast<uint2*>(oh)[i] = make_uint2(
        pack2(__float2half_rn(v.x), __float2half_rn(v.y)),
        pack2(__float2half_rn(v.z), __float2half_rn(v.w)));
}

// transpose + fp16: in fp32 [R,C] -> out fp16 [C,R]
__global__ void tconv(
    const float* __restrict__ in,
    __half* __restrict__ oh,
    int R, int C)
{
    __shared__ float t[32][33];
    const int c0 = blockIdx.x * 32, r0 = blockIdx.y * 32;
#pragma unroll
    for (int dy = 0; dy < 32; dy += 8)
        t[threadIdx.y + dy][threadIdx.x] =
            in[(long long)(r0 + threadIdx.y + dy) * C + c0 + threadIdx.x];
    __syncthreads();
#pragma unroll
    for (int dy = 0; dy < 32; dy += 8) {
        float v = t[threadIdx.x][threadIdx.y + dy];
        long long o = (long long)(c0 + threadIdx.y + dy) * R + r0 + threadIdx.x;
        oh[o] = __float2half_rn(v);
    }
}

// fp16 transpose: in [R rows, ldIn] (C cols used) -> out [C, R]; batched z
__global__ void tconvh(
    const __half* __restrict__ in, long long ldIn, long long sIn,
    __half* __restrict__ oh, long long sOut,
    int R, int C)
{
    __shared__ __half t[32][34];
    const int c0 = blockIdx.x * 32, r0 = blockIdx.y * 32;
    in += blockIdx.z * sIn; oh += blockIdx.z * sOut;
#pragma unroll
    for (int dy = 0; dy < 32; dy += 8)
        t[threadIdx.y + dy][threadIdx.x] =
            in[(long long)(r0 + threadIdx.y + dy) * ldIn + c0 + threadIdx.x];
    __syncthreads();
#pragma unroll
    for (int dy = 0; dy < 32; dy += 8) {
        long long o = (long long)(c0 + threadIdx.y + dy) * R + r0 + threadIdx.x;
        oh[o] = t[threadIdx.x][threadIdx.y + dy];
    }
}

// concat 3 biases -> g_qkvb
__global__ void bias_cat(const float* __restrict__ qb, const float* __restrict__ kb,
                         const float* __restrict__ vb, float* __restrict__ o)
{
    int i = blockIdx.x * 256 + threadIdx.x;
    if (i < DMODEL)            o[i] = qb[i];
    else if (i < 2*DMODEL)     o[i] = kb[i - DMODEL];
    else if (i < 3*DMODEL)     o[i] = vb[i - 2*DMODEL];
}

// softmax over 4096 fp16 in place
__global__ void __launch_bounds__(256) softmax_k(__half* __restrict__ S)
{
    const long long row = blockIdx.x;
    __half* p = S + row * (long long)SEQ;
    const int tid = threadIdx.x, lane = tid & 31, warp = tid >> 5;
    __shared__ float red[8];

    float v[16];
    float mx = -1e30f;
#pragma unroll
    for (int i = 0; i < 16; i++) { v[i] = __half2float(p[i*256 + tid]); mx = fmaxf(mx, v[i]); }
#pragma unroll
    for (int o = 16; o > 0; o >>= 1) mx = fmaxf(mx, __shfl_xor_sync(0xffffffffu, mx, o));
    if (!lane) red[warp] = mx;
    __syncthreads();
    mx = red[0];
#pragma unroll
    for (int w = 1; w < 8; w++) mx = fmaxf(mx, red[w]);
    __syncthreads();
    float sm = 0.f;
#pragma unroll
    for (int i = 0; i < 16; i++) { v[i] = __expf(v[i] - mx); sm += v[i]; }
#pragma unroll
    for (int o = 16; o > 0; o >>= 1) sm += __shfl_xor_sync(0xffffffffu, sm, o);
    if (!lane) red[warp] = sm;
    __syncthreads();
    float inv = __frcp_rn(red[0]+red[1]+red[2]+red[3]+red[4]+red[5]+red[6]+red[7]);
#pragma unroll
    for (int i = 0; i < 16; i++)
        p[i*256 + tid] = __float2half_rn(v[i] * inv);
}

// out = LN(X+U); optionally fp16 too
template<bool HL>
__global__ void __launch_bounds__(128) add_ln_k(
    const float* __restrict__ X, const float* __restrict__ U,
    const float* __restrict__ g, const float* __restrict__ b,
    float* __restrict__ outF, __half* __restrict__ outH)
{
    const long long row = blockIdx.x;
    const int tid = threadIdx.x, lane = tid & 31, warp = tid >> 5;
    __shared__ float red[4];

    float4 xv = reinterpret_cast<const float4*>(X + row * DMODEL)[tid];
    float4 uv = reinterpret_cast<const float4*>(U + row * DMODEL)[tid];
    float4 s = make_float4(xv.x+uv.x, xv.y+uv.y, xv.z+uv.z, xv.w+uv.w);

    float pp = s.x + s.y + s.z + s.w;
#pragma unroll
    for (int o = 16; o > 0; o >>= 1) pp += __shfl_xor_sync(0xffffffffu, pp, o);
    if (!lane) red[warp] = pp;
    __syncthreads();
    float mu = (red[0]+red[1]+red[2]+red[3]) * (1.f/DMODEL);
    __syncthreads();
    float dx = s.x-mu, dy = s.y-mu, dz = s.z-mu, dw = s.w-mu;
    pp = dx*dx + dy*dy + dz*dz + dw*dw;
#pragma unroll
    for (int o = 16; o > 0; o >>= 1) pp += __shfl_xor_sync(0xffffffffu, pp, o);
    if (!lane) red[warp] = pp;
    __syncthreads();
    float inv = rsqrtf((red[0]+red[1]+red[2]+red[3]) * (1.f/DMODEL) + 1e-5f);

    float4 gv = reinterpret_cast<const float4*>(g)[tid];
    float4 bv = reinterpret_cast<const float4*>(b)[tid];
    float4 o4;
    o4.x = dx*inv*gv.x + bv.x;
    o4.y = dy*inv*gv.y + bv.y;
    o4.z = dz*inv*gv.z + bv.z;
    o4.w = dw*inv*gv.w + bv.w;
    reinterpret_cast<float4*>(outF + row * DMODEL)[tid] = o4;
    if (HL) {
        reinterpret_cast<uint2*>(outH + row * DMODEL)[tid] = make_uint2(
            pack2(__float2half_rn(o4.x), __float2half_rn(o4.y)),
            pack2(__float2half_rn(o4.z), __float2half_rn(o4.w)));
    }
}

// ---------------------------------------------------------------------------
extern "C" void kernel_launch(void* const* d_in, const int* in_sizes, int n_in,
                              void* d_out, int out_size)
{
    (void)in_sizes; (void)n_in; (void)out_size;
    const float* x     = (const float*)d_in[0];
    const float* Wq_w  = (const float*)d_in[1];
    const float* Wq_b  = (const float*)d_in[2];
    const float* Wk_w  = (const float*)d_in[3];
    const float* Wk_b  = (const float*)d_in[4];
    const float* Wv_w  = (const float*)d_in[5];
    const float* Wv_b  = (const float*)d_in[6];
    const float* Wu_w  = (const float*)d_in[7];
    const float* Wu_b  = (const float*)d_in[8];
    const float* ln1_g = (const float*)d_in[9];
    const float* ln1_b = (const float*)d_in[10];
    const float* ff1_w = (const float*)d_in[11];
    const float* ff1_b = (const float*)d_in[12];
    const float* ff2_w = (const float*)d_in[13];
    const float* ff2_b = (const float*)d_in[14];
    const float* ln2_g = (const float*)d_in[15];
    const float* ln2_b = (const float*)d_in[16];
    float* out = (float*)d_out;

    cudaFuncSetAttribute(mma_gemm<false>, cudaFuncAttributeMaxDynamicSharedMemorySize, GEMM_SMEM);
    cudaFuncSetAttribute(mma_gemm<true>,  cudaFuncAttributeMaxDynamicSharedMemorySize, GEMM_SMEM);

#define SYM(T, n, s) T* n; { void* p_; cudaGetSymbolAddress(&p_, s); n = (T*)p_; }
    SYM(__half, s, g_s) SYM(float, u, g_u) SYM(float, h, g_h)
    SYM(__half, xh, g_xh)
    SYM(__half, qkv, g_qkv)
    SYM(__half, vth, g_vth)
    SYM(__half, ah, g_ah)
    SYM(__half, hh, g_hh)
    SYM(__half, fh, g_fh)
    SYM(__half, wqkv, g_wqkv)
    SYM(float,  qkvb, g_qkvb)
    SYM(__half, wuh, g_wuh)
    SYM(__half, f1h, g_f1h)
    SYM(__half, f2h, g_f2h)
#undef SYM

    const long long QS   = (long long)SEQ * DMODEL;
    const long long SS   = (long long)SEQ * SEQ;
    const long long QKVS = (long long)SEQ * NQKV;

    // 0: x -> fp16
    conv_h<<<(MTOT*DMODEL/4 + 255)/256, 256>>>(x, xh, MTOT*DMODEL/4);
    // 1-3: Wq|Wk|Wv transposed into combined [1536,512] fp16
    tconv<<<dim3(16,16,1), dim3(32,8)>>>(Wq_w, wqkv,                           DMODEL, DMODEL);
    tconv<<<dim3(16,16,1), dim3(32,8)>>>(Wk_w, wqkv + (size_t)DMODEL*DMODEL,   DMODEL, DMODEL);
    tconv<<<dim3(16,16,1), dim3(32,8)>>>(Wv_w, wqkv + (size_t)2*DMODEL*DMODEL, DMODEL, DMODEL);
    // 4: bias concat
    bias_cat<<<(NQKV + 255)/256, 256>>>(Wq_b, Wk_b, Wv_b, qkvb);

    // 5: fused QKV GEMM [16384,1536]
    mma_gemm<false><<<dim3(NQKV/BNT, MTOT/BMT, 1), 256, GEMM_SMEM>>>(
        xh, DMODEL, 0, wqkv, DMODEL, 0, qkvb, 1.f, nullptr, qkv, NQKV, 0, DMODEL);

    // 6: scores = QK^T/8 -> fp16
    mma_gemm<false><<<dim3(SEQ/BNT, SEQ/BMT, BATCH), 256, GEMM_SMEM>>>(
        qkv, NQKV, QKVS, qkv + DMODEL, NQKV, QKVS,
        nullptr, 0.125f, nullptr, s, SEQ, SS, DMODEL);

    // 7: softmax fp16 in place
    softmax_k<<<MTOT, 256>>>(s);

    // 8: V^T per batch
    tconvh<<<dim3(DMODEL/32, SEQ/32, BATCH), dim3(32,8)>>>(
        qkv + 2*DMODEL, NQKV, QKVS, vth, QS, SEQ, DMODEL);

    // 9: attn = P @ V
    mma_gemm<false><<<dim3(DMODEL/BNT, SEQ/BMT, BATCH), 256, GEMM_SMEM>>>(
        s, SEQ, SS, vth, SEQ, QS, nullptr, 1.f, nullptr, ah, DMODEL, QS, SEQ);

    // 10: Wu transpose; 11: unify
    tconv<<<dim3(16,16,1), dim3(32,8)>>>(Wu_w, wuh, DMODEL, DMODEL);
    mma_gemm<false><<<dim3(DMODEL/BNT, MTOT/BMT, 1), 256, GEMM_SMEM>>>(
        ah, DMODEL, 0, wuh, DMODEL, 0, Wu_b, 1.f, u, nullptr, DMODEL, 0, DMODEL);

    // 12: h = LN1(x+u)
    add_ln_k<true><<<MTOT, 128>>>(x, u, ln1_g, ln1_b, h, hh);

    // 13: ff1 weights; 14: ff1 (relu)
    tconv<<<dim3(FFDIM/32,16,1), dim3(32,8)>>>(ff1_w, f1h, DMODEL, FFDIM);
    mma_gemm<true><<<dim3(FFDIM/BNT, MTOT/BMT, 1), 256, GEMM_SMEM>>>(
        hh, DMODEL, 0, f1h, DMODEL, 0, ff1_b, 1.f, nullptr, fh, FFDIM, 0, DMODEL);

    // 15: ff2 weights; 16: ff2
    tconv<<<dim3(16,FFDIM/32,1), dim3(32,8)>>>(ff2_w, f2h, FFDIM, DMODEL);
    mma_gemm<false><<<dim3(DMODEL/BNT, MTOT/BMT, 1), 256, GEMM_SMEM>>>(
        fh, FFDIM, 0, f2h, FFDIM, 0, ff2_b, 1.f, u, nullptr, DMODEL, 0, FFDIM);

    // 17: out = LN2(h + ffwd)
    add_ln_k<false><<<MTOT, 128>>>(h, u, ln2_g, ln2_b, out, nullptr);
}

// round 15
// speedup vs baseline: 1.2986x; 1.0643x over previous
#include <cuda_runtime.h>
#include <cuda_fp16.h>
#include <cstdint>

#define SEQ     4096
#define BATCH   4
#define DMODEL  512
#define FFDIM   2048
#define MTOT    (BATCH*SEQ)
#define NQKV    (3*DMODEL)    // 1536

// GEMM tile config: CTA 128x128, 4 warps (2M x 2N), warp tile 64x64, BK=32.
// 4-stage cp.async, 64KB dynamic smem, 2 CTAs/SM (regs ~190 x 128thr x 2 < 64K).
#define BMT 128
#define BNT 128
#define NST 4
#define ASZ 8192              // 128 rows * 64B (32 fp16)
#define STG (2*ASZ)           // A + B per stage (16KB)
#define GEMM_SMEM (NST*STG)   // 64KB dynamic
#define NTHR 128

// ---------------- scratch ----------------
__device__ __align__(256) __half g_s   [(size_t)BATCH*SEQ*SEQ];     // fp16 scores/probs
__device__ __align__(256) __half g_xh  [(size_t)MTOT*DMODEL];
__device__ __align__(256) __half g_qkv [(size_t)MTOT*NQKV];         // Q|K|V fp16
__device__ __align__(256) __half g_vth [(size_t)MTOT*DMODEL];       // V^T per batch
__device__ __align__(256) __half g_ah  [(size_t)MTOT*DMODEL];
__device__ __align__(256) float  g_u   [(size_t)MTOT*DMODEL];
__device__ __align__(256) float  g_h   [(size_t)MTOT*DMODEL];
__device__ __align__(256) __half g_hh  [(size_t)MTOT*DMODEL];
__device__ __align__(256) __half g_fh  [(size_t)MTOT*FFDIM];
__device__ __align__(256) __half g_wqkv[NQKV*DMODEL];
__device__ __align__(256) float  g_qkvb[NQKV];
__device__ __align__(256) __half g_wuh [DMODEL*DMODEL];
__device__ __align__(256) __half g_f1h [FFDIM*DMODEL];
__device__ __align__(256) __half g_f2h [DMODEL*FFDIM];

// ---------------- PTX helpers ----------------
static __device__ __forceinline__ uint32_t smem_u32(const void* p) {
    uint32_t a;
    asm("{ .reg .u64 t; cvta.to.shared.u64 t, %1; cvt.u32.u64 %0, t; }" : "=r"(a) : "l"(p));
    return a;
}
#define CP_ASYNC16(saddr, gptr) \
    asm volatile("cp.async.cg.shared.global [%0], [%1], 16;" :: "r"(saddr), "l"(gptr) : "memory")
#define CP_COMMIT() asm volatile("cp.async.commit_group;" ::: "memory")
#define CP_WAIT2()  asm volatile("cp.async.wait_group 2;"  ::: "memory")

#define LDSM4(r, addr) \
    asm volatile("ldmatrix.sync.aligned.m8n8.x4.shared.b16 {%0,%1,%2,%3}, [%4];" \
        : "=r"((r)[0]), "=r"((r)[1]), "=r"((r)[2]), "=r"((r)[3]) : "r"(addr))

#define MMA16816(c, a, b) \
    asm volatile("mma.sync.aligned.m16n8k16.row.col.f32.f16.f16.f32 " \
        "{%0,%1,%2,%3}, {%4,%5,%6,%7}, {%8,%9}, {%0,%1,%2,%3};" \
        : "+f"((c)[0]), "+f"((c)[1]), "+f"((c)[2]), "+f"((c)[3]) \
        : "r"((a)[0]), "r"((a)[1]), "r"((a)[2]), "r"((a)[3]), "r"((b)[0]), "r"((b)[1]))

static __device__ __forceinline__ uint32_t pack2(__half a, __half b) {
    return (uint32_t)__half_as_ushort(a) | ((uint32_t)__half_as_ushort(b) << 16);
}

// ---------------------------------------------------------------------------
// HMMA GEMM, single-pass fp16. A:[M,K] K-major (lda). B:[N,K] K-major (ldb).
// D = alpha*A@B^T + bias; outputs fp32 and/or fp16 (ld=N_).
// CTA 128x128, BK=32, 4-stage cp.async, 4 warps (2M x 2N), warp tile 64x64.
// LDSM duplication halved vs 8-warp 64x32 (A 2x, B 2x) -> tensor-bound.
// ---------------------------------------------------------------------------
template<bool RELU>
__global__ void __launch_bounds__(NTHR, 2) mma_gemm(
    const __half* __restrict__ A, long long lda, long long sAz,
    const __half* __restrict__ B, long long ldb, long long sBz,
    const float* __restrict__ bias, float alpha,
    float* __restrict__ outF, __half* __restrict__ outH,
    int N_, long long sCz, int K)
{
    extern __shared__ __align__(1024) char smem[];
    const uint32_t sbase = smem_u32(smem);
    const int tid  = threadIdx.x;
    const int lane = tid & 31;
    const int wid  = tid >> 5;           // 0..3
    const int warp_m = (wid & 1) * 64;   // 2 M groups
    const int warp_n = (wid >> 1) * 64;  // 2 N groups

    const long long z    = blockIdx.z;
    const long long arow = (long long)blockIdx.y * BMT;
    const long long brow = (long long)blockIdx.x * BNT;

    const __half* A_z = A + z * sAz;
    const __half* B_z = B + z * sBz;

    float acc[4][8][4];
#pragma unroll
    for (int i = 0; i < 4; i++)
#pragma unroll
        for (int j = 0; j < 8; j++)
#pragma unroll
            for (int q = 0; q < 4; q++) acc[i][j][q] = 0.f;

    // cp.async: A 512 16B-chunks, B 512 chunks; 128 threads -> 4+4 per thread
    long long gA[4], gB[4]; uint32_t swz[4];
#pragma unroll
    for (int q = 0; q < 4; q++) {
        int slot = tid + q*NTHR, r = slot >> 2, c = slot & 3;
        gA[q]  = (arow + r) * lda + c*8;
        gB[q]  = (brow + r) * ldb + c*8;
        swz[q] = r*64 + (((c ^ ((r >> 1) & 3)) << 4));
    }

    const int nch = K >> 5;

#define ISSUE(ch) { \
        const int st_ = (ch) % NST; \
        const long long kof_ = (long long)(ch) * 32; \
        const uint32_t sA_ = sbase + st_*STG; \
        const uint32_t sB_ = sA_ + ASZ; \
        CP_ASYNC16(sA_ + swz[0], A_z + gA[0] + kof_); \
        CP_ASYNC16(sA_ + swz[1], A_z + gA[1] + kof_); \
        CP_ASYNC16(sA_ + swz[2], A_z + gA[2] + kof_); \
        CP_ASYNC16(sA_ + swz[3], A_z + gA[3] + kof_); \
        CP_ASYNC16(sB_ + swz[0], B_z + gB[0] + kof_); \
        CP_ASYNC16(sB_ + swz[1], B_z + gB[1] + kof_); \
        CP_ASYNC16(sB_ + swz[2], B_z + gB[2] + kof_); \
        CP_ASYNC16(sB_ + swz[3], B_z + gB[3] + kof_); }

    ISSUE(0); CP_COMMIT();
    ISSUE(1); CP_COMMIT();
    ISSUE(2); CP_COMMIT();

    const int rA   = lane & 15;
    const int kcA  = lane >> 4;
    const int swzA = (rA >> 1) & 3;
    const uint32_t aBase = (uint32_t)(warp_m + rA) * 64;
    const int rB   = ((lane >> 4) << 3) + (lane & 7);
    const int kcB  = (lane >> 3) & 1;
    const int swzB = (rB >> 1) & 3;
    const uint32_t bBase = (uint32_t)(warp_n + rB) * 64;

#pragma unroll 1
    for (int j = 0; j < nch; j++) {
        CP_WAIT2();
        __syncthreads();
        if (j + 3 < nch) { ISSUE(j + 3); }
        CP_COMMIT();

        const uint32_t sA = sbase + (j % NST) * STG;
        const uint32_t sB = sA + ASZ;
#pragma unroll
        for (int ks = 0; ks < 2; ks++) {
            uint32_t af[4][4];
            uint32_t bf[8][2];
#pragma unroll
            for (int mt = 0; mt < 4; mt++) {
                uint32_t addr = sA + aBase + mt*1024 + ((uint32_t)((ks*2 + kcA) ^ swzA) << 4);
                LDSM4(af[mt], addr);
            }
#pragma unroll
            for (int nt2 = 0; nt2 < 4; nt2++) {
                uint32_t r[4];
                uint32_t addr = sB + bBase + nt2*1024 + ((uint32_t)((ks*2 + kcB) ^ swzB) << 4);
                LDSM4(r, addr);
                bf[2*nt2][0]   = r[0]; bf[2*nt2][1]   = r[1];
                bf[2*nt2+1][0] = r[2]; bf[2*nt2+1][1] = r[3];
            }
#pragma unroll
            for (int mt = 0; mt < 4; mt++)
#pragma unroll
                for (int nt = 0; nt < 8; nt++)
                    MMA16816(acc[mt][nt], af[mt], bf[nt]);
        }
    }
#undef ISSUE

    // -------- epilogue --------
    const long long mBase = arow + warp_m + (lane >> 2);
    const int       nBase = (int)brow + warp_n + (lane & 3) * 2;
    const long long czB   = z * sCz;
#pragma unroll
    for (int mt = 0; mt < 4; mt++) {
        const long long ra = mBase + mt*16;
        const long long rb = ra + 8;
#pragma unroll
        for (int nt = 0; nt < 8; nt++) {
            const int col = nBase + nt*8;
            float v0 = acc[mt][nt][0] * alpha;
            float v1 = acc[mt][nt][1] * alpha;
            float v2 = acc[mt][nt][2] * alpha;
            float v3 = acc[mt][nt][3] * alpha;
            if (bias) {
                float2 bb = *reinterpret_cast<const float2*>(bias + col);
                v0 += bb.x; v1 += bb.y; v2 += bb.x; v3 += bb.y;
            }
            if (RELU) {
                v0 = fmaxf(v0, 0.f); v1 = fmaxf(v1, 0.f);
                v2 = fmaxf(v2, 0.f); v3 = fmaxf(v3, 0.f);
            }
            if (outF) {
                *reinterpret_cast<float2*>(outF + czB + ra*N_ + col) = make_float2(v0, v1);
                *reinterpret_cast<float2*>(outF + czB + rb*N_ + col) = make_float2(v2, v3);
            }
            if (outH) {
                *reinterpret_cast<uint32_t*>(outH + czB + ra*N_ + col) =
                    pack2(__float2half_rn(v0), __float2half_rn(v1));
                *reinterpret_cast<uint32_t*>(outH + czB + rb*N_ + col) =
                    pack2(__float2half_rn(v2), __float2half_rn(v3));
            }
        }
    }
}

// fp32 -> fp16 elementwise
__global__ void __launch_bounds__(256) conv_h(
    const float* __restrict__ in, __half* __restrict__ oh, int n4)
{
    int i = blockIdx.x * 256 + threadIdx.x;
    if (i >= n4) return;
    float4 v = reinterpret_cast<const float4*>(in)[i];
    reinterpret_cast<uint2*>(oh)[i] = make_uint2(
        pack2(__float2half_rn(v.x), __float2half_rn(v.y)),
        pack2(__float2half_rn(v.z), __float2half_rn(v.w)));
}

// transpose + fp16: in fp32 [R,C] -> out fp16 [C,R]
__global__ void tconv(
    const float* __restrict__ in,
    __half* __restrict__ oh,
    int R, int C)
{
    __shared__ float t[32][33];
    const int c0 = blockIdx.x * 32, r0 = blockIdx.y * 32;
#pragma unroll
    for (int dy = 0; dy < 32; dy += 8)
        t[threadIdx.y + dy][threadIdx.x] =
            in[(long long)(r0 + threadIdx.y + dy) * C + c0 + threadIdx.x];
    __syncthreads();
#pragma unroll
    for (int dy = 0; dy < 32; dy += 8) {
        float v = t[threadIdx.x][threadIdx.y + dy];
        long long o = (long long)(c0 + threadIdx.y + dy) * R + r0 + threadIdx.x;
        oh[o] = __float2half_rn(v);
    }
}

// fp16 transpose: in [R rows, ldIn] (C cols used) -> out [C, R]; batched z
__global__ void tconvh(
    const __half* __restrict__ in, long long ldIn, long long sIn,
    __half* __restrict__ oh, long long sOut,
    int R, int C)
{
    __shared__ __half t[32][34];
    const int c0 = blockIdx.x * 32, r0 = blockIdx.y * 32;
    in += blockIdx.z * sIn; oh += blockIdx.z * sOut;
#pragma unroll
    for (int dy = 0; dy < 32; dy += 8)
        t[threadIdx.y + dy][threadIdx.x] =
            in[(long long)(r0 + threadIdx.y + dy) * ldIn + c0 + threadIdx.x];
    __syncthreads();
#pragma unroll
    for (int dy = 0; dy < 32; dy += 8) {
        long long o = (long long)(c0 + threadIdx.y + dy) * R + r0 + threadIdx.x;
        oh[o] = t[threadIdx.x][threadIdx.y + dy];
    }
}

// concat 3 biases -> g_qkvb
__global__ void bias_cat(const float* __restrict__ qb, const float* __restrict__ kb,
                         const float* __restrict__ vb, float* __restrict__ o)
{
    int i = blockIdx.x * 256 + threadIdx.x;
    if (i < DMODEL)            o[i] = qb[i];
    else if (i < 2*DMODEL)     o[i] = kb[i - DMODEL];
    else if (i < 3*DMODEL)     o[i] = vb[i - 2*DMODEL];
}

// softmax over 4096 fp16 in place
__global__ void __launch_bounds__(256) softmax_k(__half* __restrict__ S)
{
    const long long row = blockIdx.x;
    __half* p = S + row * (long long)SEQ;
    const int tid = threadIdx.x, lane = tid & 31, warp = tid >> 5;
    __shared__ float red[8];

    float v[16];
    float mx = -1e30f;
#pragma unroll
    for (int i = 0; i < 16; i++) { v[i] = __half2float(p[i*256 + tid]); mx = fmaxf(mx, v[i]); }
#pragma unroll
    for (int o = 16; o > 0; o >>= 1) mx = fmaxf(mx, __shfl_xor_sync(0xffffffffu, mx, o));
    if (!lane) red[warp] = mx;
    __syncthreads();
    mx = red[0];
#pragma unroll
    for (int w = 1; w < 8; w++) mx = fmaxf(mx, red[w]);
    __syncthreads();
    float sm = 0.f;
#pragma unroll
    for (int i = 0; i < 16; i++) { v[i] = __expf(v[i] - mx); sm += v[i]; }
#pragma unroll
    for (int o = 16; o > 0; o >>= 1) sm += __shfl_xor_sync(0xffffffffu, sm, o);
    if (!lane) red[warp] = sm;
    __syncthreads();
    float inv = __frcp_rn(red[0]+red[1]+red[2]+red[3]+red[4]+red[5]+red[6]+red[7]);
#pragma unroll
    for (int i = 0; i < 16; i++)
        p[i*256 + tid] = __float2half_rn(v[i] * inv);
}

// out = LN(X+U); optionally fp16 too
template<bool HL>
__global__ void __launch_bounds__(128) add_ln_k(
    const float* __restrict__ X, const float* __restrict__ U,
    const float* __restrict__ g, const float* __restrict__ b,
    float* __restrict__ outF, __half* __restrict__ outH)
{
    const long long row = blockIdx.x;
    const int tid = threadIdx.x, lane = tid & 31, warp = tid >> 5;
    __shared__ float red[4];

    float4 xv = reinterpret_cast<const float4*>(X + row * DMODEL)[tid];
    float4 uv = reinterpret_cast<const float4*>(U + row * DMODEL)[tid];
    float4 s = make_float4(xv.x+uv.x, xv.y+uv.y, xv.z+uv.z, xv.w+uv.w);

    float pp = s.x + s.y + s.z + s.w;
#pragma unroll
    for (int o = 16; o > 0; o >>= 1) pp += __shfl_xor_sync(0xffffffffu, pp, o);
    if (!lane) red[warp] = pp;
    __syncthreads();
    float mu = (red[0]+red[1]+red[2]+red[3]) * (1.f/DMODEL);
    __syncthreads();
    float dx = s.x-mu, dy = s.y-mu, dz = s.z-mu, dw = s.w-mu;
    pp = dx*dx + dy*dy + dz*dz + dw*dw;
#pragma unroll
    for (int o = 16; o > 0; o >>= 1) pp += __shfl_xor_sync(0xffffffffu, pp, o);
    if (!lane) red[warp] = pp;
    __syncthreads();
    float inv = rsqrtf((red[0]+red[1]+red[2]+red[3]) * (1.f/DMODEL) + 1e-5f);

    float4 gv = reinterpret_cast<const float4*>(g)[tid];
    float4 bv = reinterpret_cast<const float4*>(b)[tid];
    float4 o4;
    o4.x = dx*inv*gv.x + bv.x;
    o4.y = dy*inv*gv.y + bv.y;
    o4.z = dz*inv*gv.z + bv.z;
    o4.w = dw*inv*gv.w + bv.w;
    reinterpret_cast<float4*>(outF + row * DMODEL)[tid] = o4;
    if (HL) {
        reinterpret_cast<uint2*>(outH + row * DMODEL)[tid] = make_uint2(
            pack2(__float2half_rn(o4.x), __float2half_rn(o4.y)),
            pack2(__float2half_rn(o4.z), __float2half_rn(o4.w)));
    }
}

// ---------------------------------------------------------------------------
extern "C" void kernel_launch(void* const* d_in, const int* in_sizes, int n_in,
                              void* d_out, int out_size)
{
    (void)in_sizes; (void)n_in; (void)out_size;
    const float* x     = (const float*)d_in[0];
    const float* Wq_w  = (const float*)d_in[1];
    const float* Wq_b  = (const float*)d_in[2];
    const float* Wk_w  = (const float*)d_in[3];
    const float* Wk_b  = (const float*)d_in[4];
    const float* Wv_w  = (const float*)d_in[5];
    const float* Wv_b  = (const float*)d_in[6];
    const float* Wu_w  = (const float*)d_in[7];
    const float* Wu_b  = (const float*)d_in[8];
    const float* ln1_g = (const float*)d_in[9];
    const float* ln1_b = (const float*)d_in[10];
    const float* ff1_w = (const float*)d_in[11];
    const float* ff1_b = (const float*)d_in[12];
    const float* ff2_w = (const float*)d_in[13];
    const float* ff2_b = (const float*)d_in[14];
    const float* ln2_g = (const float*)d_in[15];
    const float* ln2_b = (const float*)d_in[16];
    float* out = (float*)d_out;

    cudaFuncSetAttribute(mma_gemm<false>, cudaFuncAttributeMaxDynamicSharedMemorySize, GEMM_SMEM);
    cudaFuncSetAttribute(mma_gemm<true>,  cudaFuncAttributeMaxDynamicSharedMemorySize, GEMM_SMEM);

#define SYM(T, n, s) T* n; { void* p_; cudaGetSymbolAddress(&p_, s); n = (T*)p_; }
    SYM(__half, s, g_s) SYM(float, u, g_u) SYM(float, h, g_h)
    SYM(__half, xh, g_xh)
    SYM(__half, qkv, g_qkv)
    SYM(__half, vth, g_vth)
    SYM(__half, ah, g_ah)
    SYM(__half, hh, g_hh)
    SYM(__half, fh, g_fh)
    SYM(__half, wqkv, g_wqkv)
    SYM(float,  qkvb, g_qkvb)
    SYM(__half, wuh, g_wuh)
    SYM(__half, f1h, g_f1h)
    SYM(__half, f2h, g_f2h)
#undef SYM

    const long long QS   = (long long)SEQ * DMODEL;
    const long long SS   = (long long)SEQ * SEQ;
    const long long QKVS = (long long)SEQ * NQKV;

    // 0: x -> fp16
    conv_h<<<(MTOT*DMODEL/4 + 255)/256, 256>>>(x, xh, MTOT*DMODEL/4);
    // 1-3: Wq|Wk|Wv transposed into combined [1536,512] fp16
    tconv<<<dim3(16,16,1), dim3(32,8)>>>(Wq_w, wqkv,                           DMODEL, DMODEL);
    tconv<<<dim3(16,16,1), dim3(32,8)>>>(Wk_w, wqkv + (size_t)DMODEL*DMODEL,   DMODEL, DMODEL);
    tconv<<<dim3(16,16,1), dim3(32,8)>>>(Wv_w, wqkv + (size_t)2*DMODEL*DMODEL, DMODEL, DMODEL);
    // 4: bias concat
    bias_cat<<<(NQKV + 255)/256, 256>>>(Wq_b, Wk_b, Wv_b, qkvb);

    // 5: fused QKV GEMM [16384,1536]
    mma_gemm<false><<<dim3(NQKV/BNT, MTOT/BMT, 1), NTHR, GEMM_SMEM>>>(
        xh, DMODEL, 0, wqkv, DMODEL, 0, qkvb, 1.f, nullptr, qkv, NQKV, 0, DMODEL);

    // 6: scores = QK^T/8 -> fp16
    mma_gemm<false><<<dim3(SEQ/BNT, SEQ/BMT, BATCH), NTHR, GEMM_SMEM>>>(
        qkv, NQKV, QKVS, qkv + DMODEL, NQKV, QKVS,
        nullptr, 0.125f, nullptr, s, SEQ, SS, DMODEL);

    // 7: softmax fp16 in place
    softmax_k<<<MTOT, 256>>>(s);

    // 8: V^T per batch
    tconvh<<<dim3(DMODEL/32, SEQ/32, BATCH), dim3(32,8)>>>(
        qkv + 2*DMODEL, NQKV, QKVS, vth, QS, SEQ, DMODEL);

    // 9: attn = P @ V
    mma_gemm<false><<<dim3(DMODEL/BNT, SEQ/BMT, BATCH), NTHR, GEMM_SMEM>>>(
        s, SEQ, SS, vth, SEQ, QS, nullptr, 1.f, nullptr, ah, DMODEL, QS, SEQ);

    // 10: Wu transpose; 11: unify
    tconv<<<dim3(16,16,1), dim3(32,8)>>>(Wu_w, wuh, DMODEL, DMODEL);
    mma_gemm<false><<<dim3(DMODEL/BNT, MTOT/BMT, 1), NTHR, GEMM_SMEM>>>(
        ah, DMODEL, 0, wuh, DMODEL, 0, Wu_b, 1.f, u, nullptr, DMODEL, 0, DMODEL);

    // 12: h = LN1(x+u)
    add_ln_k<true><<<MTOT, 128>>>(x, u, ln1_g, ln1_b, h, hh);

    // 13: ff1 weights; 14: ff1 (relu)
    tconv<<<dim3(FFDIM/32,16,1), dim3(32,8)>>>(ff1_w, f1h, DMODEL, FFDIM);
    mma_gemm<true><<<dim3(FFDIM/BNT, MTOT/BMT, 1), NTHR, GEMM_SMEM>>>(
        hh, DMODEL, 0, f1h, DMODEL, 0, ff1_b, 1.f, nullptr, fh, FFDIM, 0, DMODEL);

    // 15: ff2 weights; 16: ff2
    tconv<<<dim3(16,FFDIM/32,1), dim3(32,8)>>>(ff2_w, f2h, FFDIM, DMODEL);
    mma_gemm<false><<<dim3(DMODEL/BNT, MTOT/BMT, 1), NTHR, GEMM_SMEM>>>(
        fh, FFDIM, 0, f2h, FFDIM, 0, ff2_b, 1.f, u, nullptr, DMODEL, 0, FFDIM);

    // 17: out = LN2(h + ffwd)
    add_ln_k<false><<<MTOT, 128>>>(h, u, ln2_g, ln2_b, out, nullptr);
}

// round 16
// speedup vs baseline: 1.3295x; 1.0238x over previous
#include <cuda_runtime.h>
#include <cuda_fp16.h>
#include <cstdint>

#define SEQ     4096
#define BATCH   4
#define DMODEL  512
#define FFDIM   2048
#define MTOT    (BATCH*SEQ)
#define NQKV    (3*DMODEL)    // 1536

// GEMM tile config: CTA 128x128, 4 warps (2M x 2N), warp tile 64x64, BK=32.
// 4-stage cp.async, 64KB dynamic smem, 2 CTAs/SM.
#define BMT 128
#define BNT 128
#define NST 4
#define ASZ 8192              // 128 rows * 64B (32 fp16)
#define STG (2*ASZ)           // A + B per stage (16KB)
#define GEMM_SMEM (NST*STG)   // 64KB dynamic
#define NTHR 128

// ---------------- scratch ----------------
__device__ __align__(256) __half g_s   [(size_t)BATCH*SEQ*SEQ];     // fp16 scores/probs
__device__ __align__(256) __half g_xh  [(size_t)MTOT*DMODEL];
__device__ __align__(256) __half g_qkv [(size_t)MTOT*NQKV];         // Q|K|V fp16
__device__ __align__(256) __half g_vth [(size_t)MTOT*DMODEL];       // V^T per batch
__device__ __align__(256) __half g_ah  [(size_t)MTOT*DMODEL];
__device__ __align__(256) float  g_u   [(size_t)MTOT*DMODEL];
__device__ __align__(256) float  g_h   [(size_t)MTOT*DMODEL];
__device__ __align__(256) __half g_hh  [(size_t)MTOT*DMODEL];
__device__ __align__(256) __half g_fh  [(size_t)MTOT*FFDIM];
__device__ __align__(256) __half g_wqkv[NQKV*DMODEL];
__device__ __align__(256) float  g_qkvb[NQKV];
__device__ __align__(256) __half g_wuh [DMODEL*DMODEL];
__device__ __align__(256) __half g_f1h [FFDIM*DMODEL];
__device__ __align__(256) __half g_f2h [DMODEL*FFDIM];

// ---------------- PTX helpers ----------------
static __device__ __forceinline__ uint32_t smem_u32(const void* p) {
    uint32_t a;
    asm("{ .reg .u64 t; cvta.to.shared.u64 t, %1; cvt.u32.u64 %0, t; }" : "=r"(a) : "l"(p));
    return a;
}
#define CP_ASYNC16(saddr, gptr) \
    asm volatile("cp.async.cg.shared.global [%0], [%1], 16;" :: "r"(saddr), "l"(gptr) : "memory")
#define CP_COMMIT() asm volatile("cp.async.commit_group;" ::: "memory")
#define CP_WAIT2()  asm volatile("cp.async.wait_group 2;"  ::: "memory")

#define LDSM4(r, addr) \
    asm volatile("ldmatrix.sync.aligned.m8n8.x4.shared.b16 {%0,%1,%2,%3}, [%4];" \
        : "=r"((r)[0]), "=r"((r)[1]), "=r"((r)[2]), "=r"((r)[3]) : "r"(addr))

#define MMA16816(c, a, b) \
    asm volatile("mma.sync.aligned.m16n8k16.row.col.f32.f16.f16.f32 " \
        "{%0,%1,%2,%3}, {%4,%5,%6,%7}, {%8,%9}, {%0,%1,%2,%3};" \
        : "+f"((c)[0]), "+f"((c)[1]), "+f"((c)[2]), "+f"((c)[3]) \
        : "r"((a)[0]), "r"((a)[1]), "r"((a)[2]), "r"((a)[3]), "r"((b)[0]), "r"((b)[1]))

static __device__ __forceinline__ uint32_t pack2(__half a, __half b) {
    return (uint32_t)__half_as_ushort(a) | ((uint32_t)__half_as_ushort(b) << 16);
}

// ---------------------------------------------------------------------------
// HMMA GEMM, single-pass fp16. A:[M,K] K-major (lda). B:[N,K] K-major (ldb).
// D = alpha*A@B^T + bias; outputs fp32 and/or fp16 (ld=N_).
// CTA 128x128, BK=32, 4-stage cp.async, 4 warps (2M x 2N), warp tile 64x64.
// ---------------------------------------------------------------------------
template<bool RELU>
__global__ void __launch_bounds__(NTHR, 2) mma_gemm(
    const __half* __restrict__ A, long long lda, long long sAz,
    const __half* __restrict__ B, long long ldb, long long sBz,
    const float* __restrict__ bias, float alpha,
    float* __restrict__ outF, __half* __restrict__ outH,
    int N_, long long sCz, int K)
{
    extern __shared__ __align__(1024) char smem[];
    const uint32_t sbase = smem_u32(smem);
    const int tid  = threadIdx.x;
    const int lane = tid & 31;
    const int wid  = tid >> 5;           // 0..3
    const int warp_m = (wid & 1) * 64;
    const int warp_n = (wid >> 1) * 64;

    const long long z    = blockIdx.z;
    const long long arow = (long long)blockIdx.y * BMT;
    const long long brow = (long long)blockIdx.x * BNT;

    const __half* A_z = A + z * sAz;
    const __half* B_z = B + z * sBz;

    float acc[4][8][4];
#pragma unroll
    for (int i = 0; i < 4; i++)
#pragma unroll
        for (int j = 0; j < 8; j++)
#pragma unroll
            for (int q = 0; q < 4; q++) acc[i][j][q] = 0.f;

    long long gA[4], gB[4]; uint32_t swz[4];
#pragma unroll
    for (int q = 0; q < 4; q++) {
        int slot = tid + q*NTHR, r = slot >> 2, c = slot & 3;
        gA[q]  = (arow + r) * lda + c*8;
        gB[q]  = (brow + r) * ldb + c*8;
        swz[q] = r*64 + (((c ^ ((r >> 1) & 3)) << 4));
    }

    const int nch = K >> 5;

#define ISSUE(ch) { \
        const int st_ = (ch) % NST; \
        const long long kof_ = (long long)(ch) * 32; \
        const uint32_t sA_ = sbase + st_*STG; \
        const uint32_t sB_ = sA_ + ASZ; \
        CP_ASYNC16(sA_ + swz[0], A_z + gA[0] + kof_); \
        CP_ASYNC16(sA_ + swz[1], A_z + gA[1] + kof_); \
        CP_ASYNC16(sA_ + swz[2], A_z + gA[2] + kof_); \
        CP_ASYNC16(sA_ + swz[3], A_z + gA[3] + kof_); \
        CP_ASYNC16(sB_ + swz[0], B_z + gB[0] + kof_); \
        CP_ASYNC16(sB_ + swz[1], B_z + gB[1] + kof_); \
        CP_ASYNC16(sB_ + swz[2], B_z + gB[2] + kof_); \
        CP_ASYNC16(sB_ + swz[3], B_z + gB[3] + kof_); }

    ISSUE(0); CP_COMMIT();
    ISSUE(1); CP_COMMIT();
    ISSUE(2); CP_COMMIT();

    const int rA   = lane & 15;
    const int kcA  = lane >> 4;
    const int swzA = (rA >> 1) & 3;
    const uint32_t aBase = (uint32_t)(warp_m + rA) * 64;
    const int rB   = ((lane >> 4) << 3) + (lane & 7);
    const int kcB  = (lane >> 3) & 1;
    const int swzB = (rB >> 1) & 3;
    const uint32_t bBase = (uint32_t)(warp_n + rB) * 64;

#pragma unroll 1
    for (int j = 0; j < nch; j++) {
        CP_WAIT2();
        __syncthreads();
        if (j + 3 < nch) { ISSUE(j + 3); }
        CP_COMMIT();

        const uint32_t sA = sbase + (j % NST) * STG;
        const uint32_t sB = sA + ASZ;
#pragma unroll
        for (int ks = 0; ks < 2; ks++) {
            uint32_t af[4][4];
            uint32_t bf[8][2];
#pragma unroll
            for (int mt = 0; mt < 4; mt++) {
                uint32_t addr = sA + aBase + mt*1024 + ((uint32_t)((ks*2 + kcA) ^ swzA) << 4);
                LDSM4(af[mt], addr);
            }
#pragma unroll
            for (int nt2 = 0; nt2 < 4; nt2++) {
                uint32_t r[4];
                uint32_t addr = sB + bBase + nt2*1024 + ((uint32_t)((ks*2 + kcB) ^ swzB) << 4);
                LDSM4(r, addr);
                bf[2*nt2][0]   = r[0]; bf[2*nt2][1]   = r[1];
                bf[2*nt2+1][0] = r[2]; bf[2*nt2+1][1] = r[3];
            }
#pragma unroll
            for (int mt = 0; mt < 4; mt++)
#pragma unroll
                for (int nt = 0; nt < 8; nt++)
                    MMA16816(acc[mt][nt], af[mt], bf[nt]);
        }
    }
#undef ISSUE

    // -------- epilogue --------
    const long long mBase = arow + warp_m + (lane >> 2);
    const int       nBase = (int)brow + warp_n + (lane & 3) * 2;
    const long long czB   = z * sCz;
#pragma unroll
    for (int mt = 0; mt < 4; mt++) {
        const long long ra = mBase + mt*16;
        const long long rb = ra + 8;
#pragma unroll
        for (int nt = 0; nt < 8; nt++) {
            const int col = nBase + nt*8;
            float v0 = acc[mt][nt][0] * alpha;
            float v1 = acc[mt][nt][1] * alpha;
            float v2 = acc[mt][nt][2] * alpha;
            float v3 = acc[mt][nt][3] * alpha;
            if (bias) {
                float2 bb = *reinterpret_cast<const float2*>(bias + col);
                v0 += bb.x; v1 += bb.y; v2 += bb.x; v3 += bb.y;
            }
            if (RELU) {
                v0 = fmaxf(v0, 0.f); v1 = fmaxf(v1, 0.f);
                v2 = fmaxf(v2, 0.f); v3 = fmaxf(v3, 0.f);
            }
            if (outF) {
                *reinterpret_cast<float2*>(outF + czB + ra*N_ + col) = make_float2(v0, v1);
                *reinterpret_cast<float2*>(outF + czB + rb*N_ + col) = make_float2(v2, v3);
            }
            if (outH) {
                *reinterpret_cast<uint32_t*>(outH + czB + ra*N_ + col) =
                    pack2(__float2half_rn(v0), __float2half_rn(v1));
                *reinterpret_cast<uint32_t*>(outH + czB + rb*N_ + col) =
                    pack2(__float2half_rn(v2), __float2half_rn(v3));
            }
        }
    }
}

// ---------------------------------------------------------------------------
// Unified prep kernel: all weight transposes + x conversion + bias concat.
// grid (1024, 1, 8), block (32, 8). Task = blockIdx.z:
//   0: x fp32 -> xh fp16 (grid-stride over uint2)
//   1: Wq^T -> wqkv[0]      2: Wk^T -> wqkv[1]    3: Wv^T -> wqkv[2]
//   4: Wu^T -> wuh          5: ff1^T -> f1h       6: ff2^T -> f2h
//   7: bias concat -> qkvb
// Transpose task: in fp32 [R,C] -> out fp16 [C,R]; flat tile id decode.
// ---------------------------------------------------------------------------
__global__ void __launch_bounds__(256) prep_k(
    const float* __restrict__ x,
    const float* __restrict__ Wq_w, const float* __restrict__ Wk_w,
    const float* __restrict__ Wv_w, const float* __restrict__ Wu_w,
    const float* __restrict__ ff1_w, const float* __restrict__ ff2_w,
    const float* __restrict__ Wq_b, const float* __restrict__ Wk_b,
    const float* __restrict__ Wv_b,
    __half* __restrict__ xh, __half* __restrict__ wqkv, __half* __restrict__ wuh,
    __half* __restrict__ f1h, __half* __restrict__ f2h, float* __restrict__ qkvb)
{
    const int tid = threadIdx.y * 32 + threadIdx.x;
    const int task = blockIdx.z;

    if (task == 0) {
        // x -> fp16: 16384*512 = 8388608 halves = 2097152 uint2 outputs
        const int n4 = MTOT*DMODEL/4;
        for (int i = blockIdx.x * 256 + tid; i < n4; i += 1024*256) {
            float4 v = reinterpret_cast<const float4*>(x)[i];
            reinterpret_cast<uint2*>(xh)[i] = make_uint2(
                pack2(__float2half_rn(v.x), __float2half_rn(v.y)),
                pack2(__float2half_rn(v.z), __float2half_rn(v.w)));
        }
        return;
    }
    if (task == 7) {
        int i = blockIdx.x * 256 + tid;
        if (i < DMODEL)            qkvb[i] = Wq_b[i];
        else if (i < 2*DMODEL)     qkvb[i] = Wk_b[i - DMODEL];
        else if (i < 3*DMODEL)     qkvb[i] = Wv_b[i - 2*DMODEL];
        return;
    }

    // transpose tasks
    const float* in; __half* oh; int R, C;
    switch (task) {
        case 1: in = Wq_w;  oh = wqkv;                           R = DMODEL; C = DMODEL; break;
        case 2: in = Wk_w;  oh = wqkv + (size_t)DMODEL*DMODEL;   R = DMODEL; C = DMODEL; break;
        case 3: in = Wv_w;  oh = wqkv + (size_t)2*DMODEL*DMODEL; R = DMODEL; C = DMODEL; break;
        case 4: in = Wu_w;  oh = wuh;  R = DMODEL; C = DMODEL; break;
        case 5: in = ff1_w; oh = f1h;  R = DMODEL; C = FFDIM;  break;
        default: in = ff2_w; oh = f2h; R = FFDIM;  C = DMODEL; break;
    }
    const int tilesX = C >> 5, tilesY = R >> 5;
    const int tile = blockIdx.x;
    if (tile >= tilesX * tilesY) return;
    const int c0 = (tile % tilesX) * 32;
    const int r0 = (tile / tilesX) * 32;

    __shared__ float t[32][33];
#pragma unroll
    for (int dy = 0; dy < 32; dy += 8)
        t[threadIdx.y + dy][threadIdx.x] =
            in[(long long)(r0 + threadIdx.y + dy) * C + c0 + threadIdx.x];
    __syncthreads();
#pragma unroll
    for (int dy = 0; dy < 32; dy += 8) {
        float v = t[threadIdx.x][threadIdx.y + dy];
        long long o = (long long)(c0 + threadIdx.y + dy) * R + r0 + threadIdx.x;
        oh[o] = __float2half_rn(v);
    }
}

// fp16 transpose: in [R rows, ldIn] (C cols used) -> out [C, R]; batched z
__global__ void tconvh(
    const __half* __restrict__ in, long long ldIn, long long sIn,
    __half* __restrict__ oh, long long sOut,
    int R, int C)
{
    __shared__ __half t[32][34];
    const int c0 = blockIdx.x * 32, r0 = blockIdx.y * 32;
    in += blockIdx.z * sIn; oh += blockIdx.z * sOut;
#pragma unroll
    for (int dy = 0; dy < 32; dy += 8)
        t[threadIdx.y + dy][threadIdx.x] =
            in[(long long)(r0 + threadIdx.y + dy) * ldIn + c0 + threadIdx.x];
    __syncthreads();
#pragma unroll
    for (int dy = 0; dy < 32; dy += 8) {
        long long o = (long long)(c0 + threadIdx.y + dy) * R + r0 + threadIdx.x;
        oh[o] = t[threadIdx.x][threadIdx.y + dy];
    }
}

// softmax over 4096 fp16 in place
__global__ void __launch_bounds__(256) softmax_k(__half* __restrict__ S)
{
    const long long row = blockIdx.x;
    __half* p = S + row * (long long)SEQ;
    const int tid = threadIdx.x, lane = tid & 31, warp = tid >> 5;
    __shared__ float red[8];

    float v[16];
    float mx = -1e30f;
#pragma unroll
    for (int i = 0; i < 16; i++) { v[i] = __half2float(p[i*256 + tid]); mx = fmaxf(mx, v[i]); }
#pragma unroll
    for (int o = 16; o > 0; o >>= 1) mx = fmaxf(mx, __shfl_xor_sync(0xffffffffu, mx, o));
    if (!lane) red[warp] = mx;
    __syncthreads();
    mx = red[0];
#pragma unroll
    for (int w = 1; w < 8; w++) mx = fmaxf(mx, red[w]);
    __syncthreads();
    float sm = 0.f;
#pragma unroll
    for (int i = 0; i < 16; i++) { v[i] = __expf(v[i] - mx); sm += v[i]; }
#pragma unroll
    for (int o = 16; o > 0; o >>= 1) sm += __shfl_xor_sync(0xffffffffu, sm, o);
    if (!lane) red[warp] = sm;
    __syncthreads();
    float inv = __frcp_rn(red[0]+red[1]+red[2]+red[3]+red[4]+red[5]+red[6]+red[7]);
#pragma unroll
    for (int i = 0; i < 16; i++)
        p[i*256 + tid] = __float2half_rn(v[i] * inv);
}

// out = LN(X+U); optionally fp16 too
template<bool HL>
__global__ void __launch_bounds__(128) add_ln_k(
    const float* __restrict__ X, const float* __restrict__ U,
    const float* __restrict__ g, const float* __restrict__ b,
    float* __restrict__ outF, __half* __restrict__ outH)
{
    const long long row = blockIdx.x;
    const int tid = threadIdx.x, lane = tid & 31, warp = tid >> 5;
    __shared__ float red[4];

    float4 xv = reinterpret_cast<const float4*>(X + row * DMODEL)[tid];
    float4 uv = reinterpret_cast<const float4*>(U + row * DMODEL)[tid];
    float4 s = make_float4(xv.x+uv.x, xv.y+uv.y, xv.z+uv.z, xv.w+uv.w);

    float pp = s.x + s.y + s.z + s.w;
#pragma unroll
    for (int o = 16; o > 0; o >>= 1) pp += __shfl_xor_sync(0xffffffffu, pp, o);
    if (!lane) red[warp] = pp;
    __syncthreads();
    float mu = (red[0]+red[1]+red[2]+red[3]) * (1.f/DMODEL);
    __syncthreads();
    float dx = s.x-mu, dy = s.y-mu, dz = s.z-mu, dw = s.w-mu;
    pp = dx*dx + dy*dy + dz*dz + dw*dw;
#pragma unroll
    for (int o = 16; o > 0; o >>= 1) pp += __shfl_xor_sync(0xffffffffu, pp, o);
    if (!lane) red[warp] = pp;
    __syncthreads();
    float inv = rsqrtf((red[0]+red[1]+red[2]+red[3]) * (1.f/DMODEL) + 1e-5f);

    float4 gv = reinterpret_cast<const float4*>(g)[tid];
    float4 bv = reinterpret_cast<const float4*>(b)[tid];
    float4 o4;
    o4.x = dx*inv*gv.x + bv.x;
    o4.y = dy*inv*gv.y + bv.y;
    o4.z = dz*inv*gv.z + bv.z;
    o4.w = dw*inv*gv.w + bv.w;
    reinterpret_cast<float4*>(outF + row * DMODEL)[tid] = o4;
    if (HL) {
        reinterpret_cast<uint2*>(outH + row * DMODEL)[tid] = make_uint2(
            pack2(__float2half_rn(o4.x), __float2half_rn(o4.y)),
            pack2(__float2half_rn(o4.z), __float2half_rn(o4.w)));
    }
}

// ---------------------------------------------------------------------------
extern "C" void kernel_launch(void* const* d_in, const int* in_sizes, int n_in,
                              void* d_out, int out_size)
{
    (void)in_sizes; (void)n_in; (void)out_size;
    const float* x     = (const float*)d_in[0];
    const float* Wq_w  = (const float*)d_in[1];
    const float* Wq_b  = (const float*)d_in[2];
    const float* Wk_w  = (const float*)d_in[3];
    const float* Wk_b  = (const float*)d_in[4];
    const float* Wv_w  = (const float*)d_in[5];
    const float* Wv_b  = (const float*)d_in[6];
    const float* Wu_w  = (const float*)d_in[7];
    const float* Wu_b  = (const float*)d_in[8];
    const float* ln1_g = (const float*)d_in[9];
    const float* ln1_b = (const float*)d_in[10];
    const float* ff1_w = (const float*)d_in[11];
    const float* ff1_b = (const float*)d_in[12];
    const float* ff2_w = (const float*)d_in[13];
    const float* ff2_b = (const float*)d_in[14];
    const float* ln2_g = (const float*)d_in[15];
    const float* ln2_b = (const float*)d_in[16];
    float* out = (float*)d_out;

    cudaFuncSetAttribute(mma_gemm<false>, cudaFuncAttributeMaxDynamicSharedMemorySize, GEMM_SMEM);
    cudaFuncSetAttribute(mma_gemm<true>,  cudaFuncAttributeMaxDynamicSharedMemorySize, GEMM_SMEM);

#define SYM(T, n, s) T* n; { void* p_; cudaGetSymbolAddress(&p_, s); n = (T*)p_; }
    SYM(__half, s, g_s) SYM(float, u, g_u) SYM(float, h, g_h)
    SYM(__half, xh, g_xh)
    SYM(__half, qkv, g_qkv)
    SYM(__half, vth, g_vth)
    SYM(__half, ah, g_ah)
    SYM(__half, hh, g_hh)
    SYM(__half, fh, g_fh)
    SYM(__half, wqkv, g_wqkv)
    SYM(float,  qkvb, g_qkvb)
    SYM(__half, wuh, g_wuh)
    SYM(__half, f1h, g_f1h)
    SYM(__half, f2h, g_f2h)
#undef SYM

    const long long QS   = (long long)SEQ * DMODEL;
    const long long SS   = (long long)SEQ * SEQ;
    const long long QKVS = (long long)SEQ * NQKV;

    // 0: ALL prep in one launch (x conv, 6 weight transposes, bias concat)
    prep_k<<<dim3(1024, 1, 8), dim3(32, 8)>>>(
        x, Wq_w, Wk_w, Wv_w, Wu_w, ff1_w, ff2_w, Wq_b, Wk_b, Wv_b,
        xh, wqkv, wuh, f1h, f2h, qkvb);

    // 1: fused QKV GEMM [16384,1536]
    mma_gemm<false><<<dim3(NQKV/BNT, MTOT/BMT, 1), NTHR, GEMM_SMEM>>>(
        xh, DMODEL, 0, wqkv, DMODEL, 0, qkvb, 1.f, nullptr, qkv, NQKV, 0, DMODEL);

    // 2: scores = QK^T/8 -> fp16
    mma_gemm<false><<<dim3(SEQ/BNT, SEQ/BMT, BATCH), NTHR, GEMM_SMEM>>>(
        qkv, NQKV, QKVS, qkv + DMODEL, NQKV, QKVS,
        nullptr, 0.125f, nullptr, s, SEQ, SS, DMODEL);

    // 3: softmax fp16 in place
    softmax_k<<<MTOT, 256>>>(s);

    // 4: V^T per batch
    tconvh<<<dim3(DMODEL/32, SEQ/32, BATCH), dim3(32,8)>>>(
        qkv + 2*DMODEL, NQKV, QKVS, vth, QS, SEQ, DMODEL);

    // 5: attn = P @ V
    mma_gemm<false><<<dim3(DMODEL/BNT, SEQ/BMT, BATCH), NTHR, GEMM_SMEM>>>(
        s, SEQ, SS, vth, SEQ, QS, nullptr, 1.f, nullptr, ah, DMODEL, QS, SEQ);

    // 6: unify
    mma_gemm<false><<<dim3(DMODEL/BNT, MTOT/BMT, 1), NTHR, GEMM_SMEM>>>(
        ah, DMODEL, 0, wuh, DMODEL, 0, Wu_b, 1.f, u, nullptr, DMODEL, 0, DMODEL);

    // 7: h = LN1(x+u)
    add_ln_k<true><<<MTOT, 128>>>(x, u, ln1_g, ln1_b, h, hh);

    // 8: ff1 (relu)
    mma_gemm<true><<<dim3(FFDIM/BNT, MTOT/BMT, 1), NTHR, GEMM_SMEM>>>(
        hh, DMODEL, 0, f1h, DMODEL, 0, ff1_b, 1.f, nullptr, fh, FFDIM, 0, DMODEL);

    // 9: ff2
    mma_gemm<false><<<dim3(DMODEL/BNT, MTOT/BMT, 1), NTHR, GEMM_SMEM>>>(
        fh, FFDIM, 0, f2h, FFDIM, 0, ff2_b, 1.f, u, nullptr, DMODEL, 0, FFDIM);

    // 10: out = LN2(h + ffwd)
    add_ln_k<false><<<MTOT, 128>>>(h, u, ln2_g, ln2_b, out, nullptr);
}

// round 17
// speedup vs baseline: 1.3354x; 1.0044x over previous
#include <cuda_runtime.h>
#include <cuda_fp16.h>
#include <cstdint>

#define SEQ     4096
#define BATCH   4
#define DMODEL  512
#define FFDIM   2048
#define MTOT    (BATCH*SEQ)
#define NQKV    (3*DMODEL)    // 1536

// GEMM tile config: CTA 128x128, 4 warps (2M x 2N), warp tile 64x64, BK=32.
// 4-stage cp.async, 64KB dynamic smem, 2 CTAs/SM.
#define BMT 128
#define BNT 128
#define NST 4
#define ASZ 8192              // 128 rows * 64B (32 fp16)
#define STG (2*ASZ)           // A + B per stage (16KB)
#define GEMM_SMEM (NST*STG)   // 64KB dynamic
#define NTHR 128

// ---------------- scratch ----------------
__device__ __align__(256) __half g_s   [(size_t)BATCH*SEQ*SEQ];     // fp16 scores/probs
__device__ __align__(256) __half g_xh  [(size_t)MTOT*DMODEL];
__device__ __align__(256) __half g_qkv [(size_t)MTOT*NQKV];         // Q|K|V fp16
__device__ __align__(256) __half g_vth [(size_t)MTOT*DMODEL];       // V^T per batch
__device__ __align__(256) __half g_ah  [(size_t)MTOT*DMODEL];
__device__ __align__(256) float  g_u   [(size_t)MTOT*DMODEL];
__device__ __align__(256) float  g_h   [(size_t)MTOT*DMODEL];
__device__ __align__(256) __half g_hh  [(size_t)MTOT*DMODEL];
__device__ __align__(256) __half g_fh  [(size_t)MTOT*FFDIM];
__device__ __align__(256) __half g_wqkv[NQKV*DMODEL];
__device__ __align__(256) float  g_qkvb[NQKV];
__device__ __align__(256) __half g_wuh [DMODEL*DMODEL];
__device__ __align__(256) __half g_f1h [FFDIM*DMODEL];
__device__ __align__(256) __half g_f2h [DMODEL*FFDIM];

// ---------------- PTX helpers ----------------
static __device__ __forceinline__ uint32_t smem_u32(const void* p) {
    uint32_t a;
    asm("{ .reg .u64 t; cvta.to.shared.u64 t, %1; cvt.u32.u64 %0, t; }" : "=r"(a) : "l"(p));
    return a;
}
#define CP_ASYNC16(saddr, gptr) \
    asm volatile("cp.async.cg.shared.global [%0], [%1], 16;" :: "r"(saddr), "l"(gptr) : "memory")
#define CP_COMMIT() asm volatile("cp.async.commit_group;" ::: "memory")
#define CP_WAIT2()  asm volatile("cp.async.wait_group 2;"  ::: "memory")

#define LDSM4(r, addr) \
    asm volatile("ldmatrix.sync.aligned.m8n8.x4.shared.b16 {%0,%1,%2,%3}, [%4];" \
        : "=r"((r)[0]), "=r"((r)[1]), "=r"((r)[2]), "=r"((r)[3]) : "r"(addr))

#define MMA16816(c, a, b) \
    asm volatile("mma.sync.aligned.m16n8k16.row.col.f32.f16.f16.f32 " \
        "{%0,%1,%2,%3}, {%4,%5,%6,%7}, {%8,%9}, {%0,%1,%2,%3};" \
        : "+f"((c)[0]), "+f"((c)[1]), "+f"((c)[2]), "+f"((c)[3]) \
        : "r"((a)[0]), "r"((a)[1]), "r"((a)[2]), "r"((a)[3]), "r"((b)[0]), "r"((b)[1]))

static __device__ __forceinline__ uint32_t pack2(__half a, __half b) {
    return (uint32_t)__half_as_ushort(a) | ((uint32_t)__half_as_ushort(b) << 16);
}

// ---------------------------------------------------------------------------
// HMMA GEMM, single-pass fp16. A:[M,K] K-major (lda). B:[N,K] K-major (ldb).
// D = alpha*A@B^T + bias; outputs fp32 and/or fp16 (ld=N_).
// CTA 128x128, BK=32, 4-stage cp.async, 4 warps (2M x 2N), warp tile 64x64.
// ---------------------------------------------------------------------------
template<bool RELU>
__global__ void __launch_bounds__(NTHR, 2) mma_gemm(
    const __half* __restrict__ A, long long lda, long long sAz,
    const __half* __restrict__ B, long long ldb, long long sBz,
    const float* __restrict__ bias, float alpha,
    float* __restrict__ outF, __half* __restrict__ outH,
    int N_, long long sCz, int K)
{
    extern __shared__ __align__(1024) char smem[];
    const uint32_t sbase = smem_u32(smem);
    const int tid  = threadIdx.x;
    const int lane = tid & 31;
    const int wid  = tid >> 5;           // 0..3
    const int warp_m = (wid & 1) * 64;
    const int warp_n = (wid >> 1) * 64;

    const long long z    = blockIdx.z;
    const long long arow = (long long)blockIdx.y * BMT;
    const long long brow = (long long)blockIdx.x * BNT;

    const __half* A_z = A + z * sAz;
    const __half* B_z = B + z * sBz;

    float acc[4][8][4];
#pragma unroll
    for (int i = 0; i < 4; i++)
#pragma unroll
        for (int j = 0; j < 8; j++)
#pragma unroll
            for (int q = 0; q < 4; q++) acc[i][j][q] = 0.f;

    long long gA[4], gB[4]; uint32_t swz[4];
#pragma unroll
    for (int q = 0; q < 4; q++) {
        int slot = tid + q*NTHR, r = slot >> 2, c = slot & 3;
        gA[q]  = (arow + r) * lda + c*8;
        gB[q]  = (brow + r) * ldb + c*8;
        swz[q] = r*64 + (((c ^ ((r >> 1) & 3)) << 4));
    }

    const int nch = K >> 5;

#define ISSUE(ch) { \
        const int st_ = (ch) % NST; \
        const long long kof_ = (long long)(ch) * 32; \
        const uint32_t sA_ = sbase + st_*STG; \
        const uint32_t sB_ = sA_ + ASZ; \
        CP_ASYNC16(sA_ + swz[0], A_z + gA[0] + kof_); \
        CP_ASYNC16(sA_ + swz[1], A_z + gA[1] + kof_); \
        CP_ASYNC16(sA_ + swz[2], A_z + gA[2] + kof_); \
        CP_ASYNC16(sA_ + swz[3], A_z + gA[3] + kof_); \
        CP_ASYNC16(sB_ + swz[0], B_z + gB[0] + kof_); \
        CP_ASYNC16(sB_ + swz[1], B_z + gB[1] + kof_); \
        CP_ASYNC16(sB_ + swz[2], B_z + gB[2] + kof_); \
        CP_ASYNC16(sB_ + swz[3], B_z + gB[3] + kof_); }

    ISSUE(0); CP_COMMIT();
    ISSUE(1); CP_COMMIT();
    ISSUE(2); CP_COMMIT();

    const int rA   = lane & 15;
    const int kcA  = lane >> 4;
    const int swzA = (rA >> 1) & 3;
    const uint32_t aBase = (uint32_t)(warp_m + rA) * 64;
    const int rB   = ((lane >> 4) << 3) + (lane & 7);
    const int kcB  = (lane >> 3) & 1;
    const int swzB = (rB >> 1) & 3;
    const uint32_t bBase = (uint32_t)(warp_n + rB) * 64;

#pragma unroll 1
    for (int j = 0; j < nch; j++) {
        CP_WAIT2();
        __syncthreads();
        if (j + 3 < nch) { ISSUE(j + 3); }
        CP_COMMIT();

        const uint32_t sA = sbase + (j % NST) * STG;
        const uint32_t sB = sA + ASZ;
#pragma unroll
        for (int ks = 0; ks < 2; ks++) {
            uint32_t af[4][4];
            uint32_t bf[8][2];
#pragma unroll
            for (int mt = 0; mt < 4; mt++) {
                uint32_t addr = sA + aBase + mt*1024 + ((uint32_t)((ks*2 + kcA) ^ swzA) << 4);
                LDSM4(af[mt], addr);
            }
#pragma unroll
            for (int nt2 = 0; nt2 < 4; nt2++) {
                uint32_t r[4];
                uint32_t addr = sB + bBase + nt2*1024 + ((uint32_t)((ks*2 + kcB) ^ swzB) << 4);
                LDSM4(r, addr);
                bf[2*nt2][0]   = r[0]; bf[2*nt2][1]   = r[1];
                bf[2*nt2+1][0] = r[2]; bf[2*nt2+1][1] = r[3];
            }
#pragma unroll
            for (int mt = 0; mt < 4; mt++)
#pragma unroll
                for (int nt = 0; nt < 8; nt++)
                    MMA16816(acc[mt][nt], af[mt], bf[nt]);
        }
    }
#undef ISSUE

    // -------- epilogue --------
    const long long mBase = arow + warp_m + (lane >> 2);
    const int       nBase = (int)brow + warp_n + (lane & 3) * 2;
    const long long czB   = z * sCz;
#pragma unroll
    for (int mt = 0; mt < 4; mt++) {
        const long long ra = mBase + mt*16;
        const long long rb = ra + 8;
#pragma unroll
        for (int nt = 0; nt < 8; nt++) {
            const int col = nBase + nt*8;
            float v0 = acc[mt][nt][0] * alpha;
            float v1 = acc[mt][nt][1] * alpha;
            float v2 = acc[mt][nt][2] * alpha;
            float v3 = acc[mt][nt][3] * alpha;
            if (bias) {
                float2 bb = *reinterpret_cast<const float2*>(bias + col);
                v0 += bb.x; v1 += bb.y; v2 += bb.x; v3 += bb.y;
            }
            if (RELU) {
                v0 = fmaxf(v0, 0.f); v1 = fmaxf(v1, 0.f);
                v2 = fmaxf(v2, 0.f); v3 = fmaxf(v3, 0.f);
            }
            if (outF) {
                *reinterpret_cast<float2*>(outF + czB + ra*N_ + col) = make_float2(v0, v1);
                *reinterpret_cast<float2*>(outF + czB + rb*N_ + col) = make_float2(v2, v3);
            }
            if (outH) {
                *reinterpret_cast<uint32_t*>(outH + czB + ra*N_ + col) =
                    pack2(__float2half_rn(v0), __float2half_rn(v1));
                *reinterpret_cast<uint32_t*>(outH + czB + rb*N_ + col) =
                    pack2(__float2half_rn(v2), __float2half_rn(v3));
            }
        }
    }
}

// ---------------------------------------------------------------------------
// Unified prep kernel (task = blockIdx.z): x conv, 6 weight transposes, bias cat.
// ---------------------------------------------------------------------------
__global__ void __launch_bounds__(256) prep_k(
    const float* __restrict__ x,
    const float* __restrict__ Wq_w, const float* __restrict__ Wk_w,
    const float* __restrict__ Wv_w, const float* __restrict__ Wu_w,
    const float* __restrict__ ff1_w, const float* __restrict__ ff2_w,
    const float* __restrict__ Wq_b, const float* __restrict__ Wk_b,
    const float* __restrict__ Wv_b,
    __half* __restrict__ xh, __half* __restrict__ wqkv, __half* __restrict__ wuh,
    __half* __restrict__ f1h, __half* __restrict__ f2h, float* __restrict__ qkvb)
{
    const int tid = threadIdx.y * 32 + threadIdx.x;
    const int task = blockIdx.z;

    if (task == 0) {
        const int n4 = MTOT*DMODEL/4;
        for (int i = blockIdx.x * 256 + tid; i < n4; i += 1024*256) {
            float4 v = reinterpret_cast<const float4*>(x)[i];
            reinterpret_cast<uint2*>(xh)[i] = make_uint2(
                pack2(__float2half_rn(v.x), __float2half_rn(v.y)),
                pack2(__float2half_rn(v.z), __float2half_rn(v.w)));
        }
        return;
    }
    if (task == 7) {
        int i = blockIdx.x * 256 + tid;
        if (i < DMODEL)            qkvb[i] = Wq_b[i];
        else if (i < 2*DMODEL)     qkvb[i] = Wk_b[i - DMODEL];
        else if (i < 3*DMODEL)     qkvb[i] = Wv_b[i - 2*DMODEL];
        return;
    }

    const float* in; __half* oh; int R, C;
    switch (task) {
        case 1: in = Wq_w;  oh = wqkv;                           R = DMODEL; C = DMODEL; break;
        case 2: in = Wk_w;  oh = wqkv + (size_t)DMODEL*DMODEL;   R = DMODEL; C = DMODEL; break;
        case 3: in = Wv_w;  oh = wqkv + (size_t)2*DMODEL*DMODEL; R = DMODEL; C = DMODEL; break;
        case 4: in = Wu_w;  oh = wuh;  R = DMODEL; C = DMODEL; break;
        case 5: in = ff1_w; oh = f1h;  R = DMODEL; C = FFDIM;  break;
        default: in = ff2_w; oh = f2h; R = FFDIM;  C = DMODEL; break;
    }
    const int tilesX = C >> 5, tilesY = R >> 5;
    const int tile = blockIdx.x;
    if (tile >= tilesX * tilesY) return;
    const int c0 = (tile % tilesX) * 32;
    const int r0 = (tile / tilesX) * 32;

    __shared__ float t[32][33];
#pragma unroll
    for (int dy = 0; dy < 32; dy += 8)
        t[threadIdx.y + dy][threadIdx.x] =
            in[(long long)(r0 + threadIdx.y + dy) * C + c0 + threadIdx.x];
    __syncthreads();
#pragma unroll
    for (int dy = 0; dy < 32; dy += 8) {
        float v = t[threadIdx.x][threadIdx.y + dy];
        long long o = (long long)(c0 + threadIdx.y + dy) * R + r0 + threadIdx.x;
        oh[o] = __float2half_rn(v);
    }
}

// fp16 transpose: in [R rows, ldIn] (C cols used) -> out [C, R]; batched z
__global__ void tconvh(
    const __half* __restrict__ in, long long ldIn, long long sIn,
    __half* __restrict__ oh, long long sOut,
    int R, int C)
{
    __shared__ __half t[32][34];
    const int c0 = blockIdx.x * 32, r0 = blockIdx.y * 32;
    in += blockIdx.z * sIn; oh += blockIdx.z * sOut;
#pragma unroll
    for (int dy = 0; dy < 32; dy += 8)
        t[threadIdx.y + dy][threadIdx.x] =
            in[(long long)(r0 + threadIdx.y + dy) * ldIn + c0 + threadIdx.x];
    __syncthreads();
#pragma unroll
    for (int dy = 0; dy < 32; dy += 8) {
        long long o = (long long)(c0 + threadIdx.y + dy) * R + r0 + threadIdx.x;
        oh[o] = t[threadIdx.x][threadIdx.y + dy];
    }
}

// ---------------------------------------------------------------------------
// Softmax over 4096 fp16 in place — fully vectorized 16B accesses.
// Thread t handles halves [t*16, t*16+16): 2 uint4 loads, 2 uint4 stores.
// ---------------------------------------------------------------------------
__global__ void __launch_bounds__(256) softmax_k(__half* __restrict__ S)
{
    const long long row = blockIdx.x;
    uint4* p4 = reinterpret_cast<uint4*>(S + row * (long long)SEQ);  // 512 uint4
    const int tid = threadIdx.x, lane = tid & 31, warp = tid >> 5;
    __shared__ float red[8];

    uint4 a = p4[tid*2], b = p4[tid*2 + 1];
    float v[16];
    {
        const uint32_t w[8] = {a.x, a.y, a.z, a.w, b.x, b.y, b.z, b.w};
#pragma unroll
        for (int i = 0; i < 8; i++) {
            float2 f = __half22float2(*reinterpret_cast<const __half2*>(&w[i]));
            v[2*i] = f.x; v[2*i+1] = f.y;
        }
    }

    float mx = v[0];
#pragma unroll
    for (int i = 1; i < 16; i++) mx = fmaxf(mx, v[i]);
#pragma unroll
    for (int o = 16; o > 0; o >>= 1) mx = fmaxf(mx, __shfl_xor_sync(0xffffffffu, mx, o));
    if (!lane) red[warp] = mx;
    __syncthreads();
    mx = red[0];
#pragma unroll
    for (int w = 1; w < 8; w++) mx = fmaxf(mx, red[w]);
    __syncthreads();

    float sm = 0.f;
#pragma unroll
    for (int i = 0; i < 16; i++) { v[i] = __expf(v[i] - mx); sm += v[i]; }
#pragma unroll
    for (int o = 16; o > 0; o >>= 1) sm += __shfl_xor_sync(0xffffffffu, sm, o);
    if (!lane) red[warp] = sm;
    __syncthreads();
    float inv = __frcp_rn(red[0]+red[1]+red[2]+red[3]+red[4]+red[5]+red[6]+red[7]);

    uint32_t o8[8];
#pragma unroll
    for (int i = 0; i < 8; i++)
        o8[i] = pack2(__float2half_rn(v[2*i] * inv), __float2half_rn(v[2*i+1] * inv));
    p4[tid*2]     = make_uint4(o8[0], o8[1], o8[2], o8[3]);
    p4[tid*2 + 1] = make_uint4(o8[4], o8[5], o8[6], o8[7]);
}

// out = LN(X+U); optionally fp16 too
template<bool HL>
__global__ void __launch_bounds__(128) add_ln_k(
    const float* __restrict__ X, const float* __restrict__ U,
    const float* __restrict__ g, const float* __restrict__ b,
    float* __restrict__ outF, __half* __restrict__ outH)
{
    const long long row = blockIdx.x;
    const int tid = threadIdx.x, lane = tid & 31, warp = tid >> 5;
    __shared__ float red[4];

    float4 xv = reinterpret_cast<const float4*>(X + row * DMODEL)[tid];
    float4 uv = reinterpret_cast<const float4*>(U + row * DMODEL)[tid];
    float4 s = make_float4(xv.x+uv.x, xv.y+uv.y, xv.z+uv.z, xv.w+uv.w);

    float pp = s.x + s.y + s.z + s.w;
#pragma unroll
    for (int o = 16; o > 0; o >>= 1) pp += __shfl_xor_sync(0xffffffffu, pp, o);
    if (!lane) red[warp] = pp;
    __syncthreads();
    float mu = (red[0]+red[1]+red[2]+red[3]) * (1.f/DMODEL);
    __syncthreads();
    float dx = s.x-mu, dy = s.y-mu, dz = s.z-mu, dw = s.w-mu;
    pp = dx*dx + dy*dy + dz*dz + dw*dw;
#pragma unroll
    for (int o = 16; o > 0; o >>= 1) pp += __shfl_xor_sync(0xffffffffu, pp, o);
    if (!lane) red[warp] = pp;
    __syncthreads();
    float inv = rsqrtf((red[0]+red[1]+red[2]+red[3]) * (1.f/DMODEL) + 1e-5f);

    float4 gv = reinterpret_cast<const float4*>(g)[tid];
    float4 bv = reinterpret_cast<const float4*>(b)[tid];
    float4 o4;
    o4.x = dx*inv*gv.x + bv.x;
    o4.y = dy*inv*gv.y + bv.y;
    o4.z = dz*inv*gv.z + bv.z;
    o4.w = dw*inv*gv.w + bv.w;
    reinterpret_cast<float4*>(outF + row * DMODEL)[tid] = o4;
    if (HL) {
        reinterpret_cast<uint2*>(outH + row * DMODEL)[tid] = make_uint2(
            pack2(__float2half_rn(o4.x), __float2half_rn(o4.y)),
            pack2(__float2half_rn(o4.z), __float2half_rn(o4.w)));
    }
}

// ---------------------------------------------------------------------------
extern "C" void kernel_launch(void* const* d_in, const int* in_sizes, int n_in,
                              void* d_out, int out_size)
{
    (void)in_sizes; (void)n_in; (void)out_size;
    const float* x     = (const float*)d_in[0];
    const float* Wq_w  = (const float*)d_in[1];
    const float* Wq_b  = (const float*)d_in[2];
    const float* Wk_w  = (const float*)d_in[3];
    const float* Wk_b  = (const float*)d_in[4];
    const float* Wv_w  = (const float*)d_in[5];
    const float* Wv_b  = (const float*)d_in[6];
    const float* Wu_w  = (const float*)d_in[7];
    const float* Wu_b  = (const float*)d_in[8];
    const float* ln1_g = (const float*)d_in[9];
    const float* ln1_b = (const float*)d_in[10];
    const float* ff1_w = (const float*)d_in[11];
    const float* ff1_b = (const float*)d_in[12];
    const float* ff2_w = (const float*)d_in[13];
    const float* ff2_b = (const float*)d_in[14];
    const float* ln2_g = (const float*)d_in[15];
    const float* ln2_b = (const float*)d_in[16];
    float* out = (float*)d_out;

    cudaFuncSetAttribute(mma_gemm<false>, cudaFuncAttributeMaxDynamicSharedMemorySize, GEMM_SMEM);
    cudaFuncSetAttribute(mma_gemm<true>,  cudaFuncAttributeMaxDynamicSharedMemorySize, GEMM_SMEM);

#define SYM(T, n, s) T* n; { void* p_; cudaGetSymbolAddress(&p_, s); n = (T*)p_; }
    SYM(__half, s, g_s) SYM(float, u, g_u) SYM(float, h, g_h)
    SYM(__half, xh, g_xh)
    SYM(__half, qkv, g_qkv)
    SYM(__half, vth, g_vth)
    SYM(__half, ah, g_ah)
    SYM(__half, hh, g_hh)
    SYM(__half, fh, g_fh)
    SYM(__half, wqkv, g_wqkv)
    SYM(float,  qkvb, g_qkvb)
    SYM(__half, wuh, g_wuh)
    SYM(__half, f1h, g_f1h)
    SYM(__half, f2h, g_f2h)
#undef SYM

    const long long QS   = (long long)SEQ * DMODEL;
    const long long SS   = (long long)SEQ * SEQ;
    const long long QKVS = (long long)SEQ * NQKV;

    // 0: ALL prep in one launch
    prep_k<<<dim3(1024, 1, 8), dim3(32, 8)>>>(
        x, Wq_w, Wk_w, Wv_w, Wu_w, ff1_w, ff2_w, Wq_b, Wk_b, Wv_b,
        xh, wqkv, wuh, f1h, f2h, qkvb);

    // 1: fused QKV GEMM [16384,1536]
    mma_gemm<false><<<dim3(NQKV/BNT, MTOT/BMT, 1), NTHR, GEMM_SMEM>>>(
        xh, DMODEL, 0, wqkv, DMODEL, 0, qkvb, 1.f, nullptr, qkv, NQKV, 0, DMODEL);

    // 2: scores = QK^T/8 -> fp16
    mma_gemm<false><<<dim3(SEQ/BNT, SEQ/BMT, BATCH), NTHR, GEMM_SMEM>>>(
        qkv, NQKV, QKVS, qkv + DMODEL, NQKV, QKVS,
        nullptr, 0.125f, nullptr, s, SEQ, SS, DMODEL);

    // 3: softmax fp16 in place (vectorized)
    softmax_k<<<MTOT, 256>>>(s);

    // 4: V^T per batch
    tconvh<<<dim3(DMODEL/32, SEQ/32, BATCH), dim3(32,8)>>>(
        qkv + 2*DMODEL, NQKV, QKVS, vth, QS, SEQ, DMODEL);

    // 5: attn = P @ V
    mma_gemm<false><<<dim3(DMODEL/BNT, SEQ/BMT, BATCH), NTHR, GEMM_SMEM>>>(
        s, SEQ, SS, vth, SEQ, QS, nullptr, 1.f, nullptr, ah, DMODEL, QS, SEQ);

    // 6: unify
    mma_gemm<false><<<dim3(DMODEL/BNT, MTOT/BMT, 1), NTHR, GEMM_SMEM>>>(
        ah, DMODEL, 0, wuh, DMODEL, 0, Wu_b, 1.f, u, nullptr, DMODEL, 0, DMODEL);

    // 7: h = LN1(x+u)
    add_ln_k<true><<<MTOT, 128>>>(x, u, ln1_g, ln1_b, h, hh);

    // 8: ff1 (relu)
    mma_gemm<true><<<dim3(FFDIM/BNT, MTOT/BMT, 1), NTHR, GEMM_SMEM>>>(
        hh, DMODEL, 0, f1h, DMODEL, 0, ff1_b, 1.f, nullptr, fh, FFDIM, 0, DMODEL);

    // 9: ff2
    mma_gemm<false><<<dim3(DMODEL/BNT, MTOT/BMT, 1), NTHR, GEMM_SMEM>>>(
        fh, FFDIM, 0, f2h, FFDIM, 0, ff2_b, 1.f, u, nullptr, DMODEL, 0, FFDIM);

    // 10: out = LN2(h + ffwd)
    add_ln_k<false><<<MTOT, 128>>>(h, u, ln2_g, ln2_b, out, nullptr);
}